// round 3
// baseline (speedup 1.0000x reference)
#include <cuda_runtime.h>
#include <cuda_bf16.h>
#include <math.h>

// Problem constants (fixed shapes per reference)
#define B_    32
#define CIN   128
#define COUT  256
#define HW    3136        // 56*56
#define HDIM  56
#define KK    9           // 3x3
#define EXP_  4
#define RDIM  16
#define KERN_PER_B (COUT*CIN*KK)   // 294912 floats per sample

// Scratch (allocation-free rule: __device__ globals)
__device__ float g_routing[B_ * EXP_];
__device__ float g_kern[B_ * KERN_PER_B];   // ~37.7 MB

// ---------------------------------------------------------------------------
// Kernel 1: routing = softmax( MLP( GAP(x) ) / 30 )
// grid = 32 (one block per sample), block = 256 (8 warps)
// ---------------------------------------------------------------------------
__global__ void routing_kernel(const float* __restrict__ x,
                               const float* __restrict__ w1,
                               const float* __restrict__ b1,
                               const float* __restrict__ w2,
                               const float* __restrict__ b2) {
    __shared__ float sgap[CIN];
    __shared__ float sh[RDIM];
    __shared__ float slog[EXP_];

    const int b    = blockIdx.x;
    const int tid  = threadIdx.x;
    const int warp = tid >> 5;
    const int lane = tid & 31;

    const float* xb = x + (size_t)b * CIN * HW;

    // per-channel mean: each warp owns channels warp, warp+8, ...
    for (int c = warp; c < CIN; c += 8) {
        const float* xc = xb + (size_t)c * HW;
        float s = 0.f;
        for (int i = lane; i < HW; i += 32) s += xc[i];
        #pragma unroll
        for (int o = 16; o; o >>= 1) s += __shfl_xor_sync(0xffffffffu, s, o);
        if (lane == 0) sgap[c] = s * (1.0f / (float)HW);
    }
    __syncthreads();

    if (tid < RDIM) {
        float a = b1[tid];
        const float* wr = w1 + tid * CIN;
        #pragma unroll 8
        for (int c = 0; c < CIN; c++) a = fmaf(wr[c], sgap[c], a);
        sh[tid] = fmaxf(a, 0.f);
    }
    __syncthreads();

    if (tid < EXP_) {
        float a = b2[tid];
        const float* wr = w2 + tid * RDIM;
        #pragma unroll
        for (int r = 0; r < RDIM; r++) a = fmaf(wr[r], sh[r], a);
        slog[tid] = a;
    }
    __syncthreads();

    if (tid == 0) {
        float m = fmaxf(fmaxf(slog[0], slog[1]), fmaxf(slog[2], slog[3]));
        float e[EXP_];
        float ssum = 0.f;
        #pragma unroll
        for (int i = 0; i < EXP_; i++) {
            e[i] = expf((slog[i] - m) * (1.0f / 30.0f));
            ssum += e[i];
        }
        float inv = 1.0f / ssum;
        #pragma unroll
        for (int i = 0; i < EXP_; i++) g_routing[b * EXP_ + i] = e[i] * inv;
    }
}

// ---------------------------------------------------------------------------
// Kernel 2: kern[b] = sum_e routing[b][e] * convs[e]   (float4, coalesced)
// ---------------------------------------------------------------------------
__global__ void mix_kernel(const float* __restrict__ convs) {
    const int per_b4 = KERN_PER_B / 4;                 // 73728
    int i = blockIdx.x * blockDim.x + threadIdx.x;     // float4 index
    if (i >= B_ * per_b4) return;
    int b = i / per_b4;
    int j = i - b * per_b4;

    float r0 = g_routing[b * EXP_ + 0];
    float r1 = g_routing[b * EXP_ + 1];
    float r2 = g_routing[b * EXP_ + 2];
    float r3 = g_routing[b * EXP_ + 3];

    const float4* c4 = (const float4*)convs;
    float4 a0 = c4[0 * per_b4 + j];
    float4 a1 = c4[1 * per_b4 + j];
    float4 a2 = c4[2 * per_b4 + j];
    float4 a3 = c4[3 * per_b4 + j];

    float4 o;
    o.x = fmaf(r0, a0.x, fmaf(r1, a1.x, fmaf(r2, a2.x, r3 * a3.x)));
    o.y = fmaf(r0, a0.y, fmaf(r1, a1.y, fmaf(r2, a2.y, r3 * a3.y)));
    o.z = fmaf(r0, a0.z, fmaf(r1, a1.z, fmaf(r2, a2.z, r3 * a3.z)));
    o.w = fmaf(r0, a0.w, fmaf(r1, a1.w, fmaf(r2, a2.w, r3 * a3.w)));
    ((float4*)g_kern)[i] = o;
}

// ---------------------------------------------------------------------------
// Kernel 3: per-sample 3x3 conv, pad 1.
// Block tile: 64 Cout x (4 rows x 56 cols) = 64 x 224 outputs.
// Cin chunked by 16. 256 threads = (tx=16 cout-lanes, ty=16 spatial-lanes).
// Each thread: acc[4 cout][14 cols].
// Smem: weights [ci][9][co] (pad 65), input [ci][6][58] with halo;
//       epilogue re-staged through smem for coalesced stores.
// ---------------------------------------------------------------------------
#define CI_CHUNK 16
#define CT 64
#define WS_PAD 65
#define WS_FLOATS (CI_CHUNK * KK * WS_PAD)       // 9360
#define XS_FLOATS (CI_CHUNK * 6 * 58)            // 5568
#define SMEM_FLOATS (WS_FLOATS + XS_FLOATS)      // 14928 -> 59712 B
#define SOUT_FLOATS (CT * 225)                   // 14400 (fits in same buffer)

__global__ __launch_bounds__(256, 2)
void conv_kernel(const float* __restrict__ x, float* __restrict__ out) {
    extern __shared__ float smem[];
    float* ws = smem;                 // [ci][k][co] padded
    float* xs = smem + WS_FLOATS;     // [ci][6][58]

    const int tx  = threadIdx.x;      // cout lane
    const int ty  = threadIdx.y;      // spatial lane
    const int tid = ty * 16 + tx;

    const int r0  = blockIdx.x * 4;       // 14 row tiles
    const int co0 = blockIdx.y * CT;      // 4 cout tiles
    const int b   = blockIdx.z;

    const int rl   = ty >> 2;             // local output row 0..3
    const int col0 = (ty & 3) * 14;       // starting col of this thread's 14

    float acc[4][14];
    #pragma unroll
    for (int m = 0; m < 4; m++)
        #pragma unroll
        for (int j = 0; j < 14; j++) acc[m][j] = 0.f;

    const float* kernb = g_kern + (size_t)b * KERN_PER_B + (size_t)co0 * (CIN * KK);
    const float* xb    = x + (size_t)b * CIN * HW;

    for (int ci0 = 0; ci0 < CIN; ci0 += CI_CHUNK) {
        // --- load weights: [64 co][144 (ci*9+k)] -> ws[(ci*9+k)*65 + co]
        #pragma unroll 4
        for (int t = tid; t < CT * (CI_CHUNK * KK); t += 256) {
            int co = t / 144;
            int j  = t - co * 144;         // j = ci*9 + k
            ws[j * WS_PAD + co] = kernb[co * (CIN * KK) + ci0 * KK + j];
        }
        // --- load input tile with halo: xs[ci][lr][lc], rows r0-1..r0+4, cols -1..56
        #pragma unroll 4
        for (int t = tid; t < XS_FLOATS; t += 256) {
            int ci  = t / 348;
            int rem = t - ci * 348;
            int lr  = rem / 58;
            int lc  = rem - lr * 58;
            int gr  = r0 - 1 + lr;
            int gc  = lc - 1;
            float v = 0.f;
            if ((unsigned)gr < 56u && (unsigned)gc < 56u)
                v = xb[(ci0 + ci) * HW + gr * HDIM + gc];
            xs[t] = v;
        }
        __syncthreads();

        // --- compute
        for (int ci = 0; ci < CI_CHUNK; ci++) {
            #pragma unroll
            for (int kh = 0; kh < 3; kh++) {
                float xr[16];
                const float* xrow = xs + ci * 348 + (rl + kh) * 58 + col0;
                #pragma unroll
                for (int u = 0; u < 16; u++) xr[u] = xrow[u];
                #pragma unroll
                for (int kw = 0; kw < 3; kw++) {
                    const float* wsl = ws + (ci * 9 + kh * 3 + kw) * WS_PAD + tx;
                    float w0 = wsl[0];
                    float w1v = wsl[16];
                    float w2v = wsl[32];
                    float w3v = wsl[48];
                    #pragma unroll
                    for (int j = 0; j < 14; j++) {
                        float xv = xr[j + kw];
                        acc[0][j] = fmaf(w0,  xv, acc[0][j]);
                        acc[1][j] = fmaf(w1v, xv, acc[1][j]);
                        acc[2][j] = fmaf(w2v, xv, acc[2][j]);
                        acc[3][j] = fmaf(w3v, xv, acc[3][j]);
                    }
                }
            }
        }
        __syncthreads();
    }

    // --- epilogue: stage through smem for coalesced global stores
    float* sout = smem;     // 64 x 225 (pad) floats
    #pragma unroll
    for (int m = 0; m < 4; m++) {
        int co = tx + 16 * m;
        #pragma unroll
        for (int j = 0; j < 14; j++)
            sout[co * 225 + ty * 14 + j] = acc[m][j];
    }
    __syncthreads();

    float* outb = out + ((size_t)(b * COUT + co0)) * HW + r0 * HDIM;
    #pragma unroll 4
    for (int t = tid; t < CT * 224; t += 256) {
        int co = t / 224;
        int s  = t - co * 224;
        outb[co * HW + s] = sout[co * 225 + s];
    }
}

// ---------------------------------------------------------------------------
extern "C" void kernel_launch(void* const* d_in, const int* in_sizes, int n_in,
                              void* d_out, int out_size) {
    const float* x     = (const float*)d_in[0];
    const float* convs = (const float*)d_in[1];
    const float* w1    = (const float*)d_in[2];
    const float* b1    = (const float*)d_in[3];
    const float* w2    = (const float*)d_in[4];
    const float* b2    = (const float*)d_in[5];
    float* out = (float*)d_out;

    (void)in_sizes; (void)n_in; (void)out_size;

    cudaFuncSetAttribute(conv_kernel,
                         cudaFuncAttributeMaxDynamicSharedMemorySize,
                         SMEM_FLOATS * (int)sizeof(float));

    routing_kernel<<<B_, 256>>>(x, w1, b1, w2, b2);

    int n4 = B_ * KERN_PER_B / 4;
    mix_kernel<<<(n4 + 255) / 256, 256>>>(convs);

    dim3 grid(14, COUT / CT, B_);
    dim3 block(16, 16);
    conv_kernel<<<grid, block, SMEM_FLOATS * (int)sizeof(float)>>>(x, out);
}

// round 5
// speedup vs baseline: 2.7213x; 2.7213x over previous
#include <cuda_runtime.h>
#include <cuda_bf16.h>
#include <cstdint>

// ---------------- problem constants ----------------
#define B_    32
#define CIN   128
#define COUT  256
#define HW    3136
#define HDIM  56
#define PD    58          // padded dim
#define PPIX  (PD*PD)     // 3364
#define EXP_  4
#define RDIM  16
#define NT    128         // GEMM N tile (pixels)
#define NTILES 25         // ceil(3136/128)

// ---------------- device scratch (no allocs allowed) ----------------
__device__ float g_routing[B_ * EXP_];
__device__ float g_gap[B_ * CIN];
// W split, GEMM-tile layout: [b][k(9)][cic(2)][co(256)][cii(64)]
__device__ __align__(16) __nv_bfloat16 g_whi[(size_t)B_ * 9 * 2 * COUT * 64];
__device__ __align__(16) __nv_bfloat16 g_wlo[(size_t)B_ * 9 * 2 * COUT * 64];
// X split, padded channel-last: [b][pp(3364)][ci(128)]
__device__ __align__(16) __nv_bfloat16 g_xhi[(size_t)B_ * PPIX * CIN];
__device__ __align__(16) __nv_bfloat16 g_xlo[(size_t)B_ * PPIX * CIN];

// ---------------- helpers ----------------
__device__ __forceinline__ uint32_t smem_u32(const void* p) {
    uint32_t a;
    asm("{ .reg .u64 t; cvta.to.shared.u64 t, %1; cvt.u32.u64 %0, t; }" : "=r"(a) : "l"(p));
    return a;
}
#define SW128(o) ((uint32_t)(o) ^ ((((uint32_t)(o)) >> 3) & 0x70))

__device__ __forceinline__ void cp16(uint32_t dst, const void* src, int sz) {
    asm volatile("cp.async.cg.shared.global [%0], [%1], 16, %2;"
                 :: "r"(dst), "l"(src), "r"(sz) : "memory");
}
#define CP_COMMIT() asm volatile("cp.async.commit_group;" ::: "memory")
#define CP_WAIT(n)  asm volatile("cp.async.wait_group %0;" :: "n"(n) : "memory")

#define LDSM4(r, a)                                                              \
    asm volatile("ldmatrix.sync.aligned.m8n8.x4.shared.b16 {%0,%1,%2,%3}, [%4];" \
        : "=r"((r)[0]), "=r"((r)[1]), "=r"((r)[2]), "=r"((r)[3]) : "r"(a))

__device__ __forceinline__ void mma16816(float* c, const uint32_t* a,
                                         uint32_t b0, uint32_t b1) {
    asm volatile(
        "mma.sync.aligned.m16n8k16.row.col.f32.bf16.bf16.f32 "
        "{%0,%1,%2,%3}, {%4,%5,%6,%7}, {%8,%9}, {%0,%1,%2,%3};"
        : "+f"(c[0]), "+f"(c[1]), "+f"(c[2]), "+f"(c[3])
        : "r"(a[0]), "r"(a[1]), "r"(a[2]), "r"(a[3]), "r"(b0), "r"(b1));
}

// ---------------------------------------------------------------------------
// Kernel 1a: per-(b,c) global average pool.  grid (128, 32), 128 threads.
// ---------------------------------------------------------------------------
__global__ void gap_kernel(const float* __restrict__ x) {
    int c = blockIdx.x, b = blockIdx.y;
    const float* p = x + ((size_t)(b * CIN + c)) * HW;
    float s = 0.f;
    for (int i = threadIdx.x; i < HW; i += 128) s += p[i];
    #pragma unroll
    for (int o = 16; o; o >>= 1) s += __shfl_xor_sync(0xffffffffu, s, o);
    __shared__ float ws[4];
    int wid = threadIdx.x >> 5;
    if ((threadIdx.x & 31) == 0) ws[wid] = s;
    __syncthreads();
    if (threadIdx.x == 0)
        g_gap[b * CIN + c] = (ws[0] + ws[1] + ws[2] + ws[3]) * (1.0f / (float)HW);
}

// ---------------------------------------------------------------------------
// Kernel 1b: router MLP + softmax.  grid 32, 32 threads.
// ---------------------------------------------------------------------------
__global__ void router_kernel(const float* __restrict__ w1, const float* __restrict__ b1,
                              const float* __restrict__ w2, const float* __restrict__ b2) {
    int b = blockIdx.x, t = threadIdx.x;
    __shared__ float h[RDIM], lg[EXP_];
    if (t < RDIM) {
        float a = b1[t];
        const float* wr = w1 + t * CIN;
        const float* gp = g_gap + b * CIN;
        #pragma unroll 8
        for (int c = 0; c < CIN; c++) a = fmaf(wr[c], gp[c], a);
        h[t] = fmaxf(a, 0.f);
    }
    __syncwarp();
    if (t < EXP_) {
        float a = b2[t];
        #pragma unroll
        for (int r = 0; r < RDIM; r++) a = fmaf(w2[t * RDIM + r], h[r], a);
        lg[t] = a;
    }
    __syncwarp();
    if (t == 0) {
        float m = fmaxf(fmaxf(lg[0], lg[1]), fmaxf(lg[2], lg[3]));
        float e[EXP_], ss = 0.f;
        #pragma unroll
        for (int i = 0; i < EXP_; i++) { e[i] = expf((lg[i] - m) * (1.0f / 30.0f)); ss += e[i]; }
        float inv = 1.0f / ss;
        #pragma unroll
        for (int i = 0; i < EXP_; i++) g_routing[b * EXP_ + i] = e[i] * inv;
    }
}

// ---------------------------------------------------------------------------
// Kernel 2: mix experts + hi/lo bf16 split, written in GEMM tile layout.
// ---------------------------------------------------------------------------
__global__ void wmix_kernel(const float* __restrict__ convs) {
    int co = blockIdx.x;
    int tid = threadIdx.x;
    __shared__ float se[EXP_][CIN * 9];
    for (int e = 0; e < EXP_; e++) {
        const float* src = convs + ((size_t)(e * COUT + co)) * (CIN * 9);
        for (int i = tid; i < CIN * 9; i += 288) se[e][i] = src[i];
    }
    __syncthreads();
    for (int b = 0; b < B_; b++) {
        float r0 = g_routing[b * EXP_ + 0], r1 = g_routing[b * EXP_ + 1];
        float r2 = g_routing[b * EXP_ + 2], r3 = g_routing[b * EXP_ + 3];
        #pragma unroll
        for (int it = 0; it < 4; it++) {
            int idx = it * 288 + tid;          // 1152 = 4*288
            int k = idx >> 7;                  // 0..8
            int ci = idx & 127;
            int j = ci * 9 + k;
            float v = fmaf(r0, se[0][j], fmaf(r1, se[1][j], fmaf(r2, se[2][j], r3 * se[3][j])));
            __nv_bfloat16 hi = __float2bfloat16(v);
            __nv_bfloat16 lo = __float2bfloat16(v - __bfloat162float(hi));
            size_t d = ((((size_t)b * 9 + k) * 2 + (ci >> 6)) * COUT + co) * 64 + (ci & 63);
            g_whi[d] = hi;
            g_wlo[d] = lo;
        }
    }
}

// ---------------------------------------------------------------------------
// Kernel 3a: transpose + split x -> padded channel-last bf16 (interior).
// ---------------------------------------------------------------------------
__global__ void xsplit_kernel(const float* __restrict__ x) {
    __shared__ float s[CIN][33];
    int p0 = blockIdx.x * 32, b = blockIdx.y;
    int tid = threadIdx.x, lane = tid & 31, grp8 = tid >> 5;
    #pragma unroll 4
    for (int pass = 0; pass < 16; pass++) {
        int ci = pass * 8 + grp8;
        s[ci][lane] = x[((size_t)(b * CIN + ci)) * HW + p0 + lane];
    }
    __syncthreads();
    int pl = tid >> 3, g = tid & 7;
    int p = p0 + pl;
    int r = p / 56, c = p - r * 56;
    int pp = (r + 1) * PD + (c + 1);
    size_t base = ((size_t)(b * PPIX + pp)) * CIN + g * 16;
    __nv_bfloat16 hi[16], lo[16];
    #pragma unroll
    for (int u = 0; u < 16; u++) {
        float v = s[g * 16 + u][pl];
        hi[u] = __float2bfloat16(v);
        lo[u] = __float2bfloat16(v - __bfloat162float(hi[u]));
    }
    *(uint4*)(g_xhi + base)     = *(uint4*)(hi);
    *(uint4*)(g_xhi + base + 8) = *(uint4*)(hi + 8);
    *(uint4*)(g_xlo + base)     = *(uint4*)(lo);
    *(uint4*)(g_xlo + base + 8) = *(uint4*)(lo + 8);
}

// Kernel 3b: zero the border pixels per sample.
__global__ void xborder_kernel() {
    int b = blockIdx.x;
    uint4 z = {0, 0, 0, 0};
    for (int idx = threadIdx.x; idx < 228 * 16; idx += 256) {
        int i = idx >> 4, u = idx & 15;
        int pp;
        if (i < 58)       pp = i;
        else if (i < 116) pp = 57 * PD + (i - 58);
        else { int j = i - 116; pp = (1 + (j >> 1)) * PD + (j & 1) * 57; }
        size_t base = ((size_t)(b * PPIX + pp)) * CIN;
        ((uint4*)(g_xhi + base))[u] = z;
        ((uint4*)(g_xlo + base))[u] = z;
    }
}

// ---------------------------------------------------------------------------
// Kernel 4: mma.sync bf16x3 implicit-GEMM conv.
// grid (25, 2, 32), 256 threads (8 warps).  CTA tile 128co x 128px.
// K = 18 chunks of 64 (9 taps x 2 ci halves), cp.async double-buffered.
// Warp tile 32co x 64px; acc fp32; splits hi*hi + hi*lo + lo*hi.
// Smem buffer (64KB): Ah|Al|Bh|Bl each 16KB, rows of 128B, SW128 swizzle.
// ---------------------------------------------------------------------------
#define TILE_B   16384
#define BUF_B    (4 * TILE_B)
#define SMEM_DYN (2 * BUF_B + 1024)

__global__ __launch_bounds__(256, 1)
void gemm_kernel(float* __restrict__ out) {
    extern __shared__ char dyn[];
    uint32_t sb = smem_u32(dyn);
    uint32_t ab = (sb + 1023u) & ~1023u;
    char* mem = dyn + (ab - sb);

    const int tid = threadIdx.x, w = tid >> 5, lane = tid & 31;
    const int wm = w & 3, wn = w >> 2;          // warp grid 4m x 2n
    const int ntile = blockIdx.x, cotile = blockIdx.y, b = blockIdx.z;
    const int p0 = ntile * NT;

    // ---- precompute B-load row offsets (tap (0,0) base) for this thread
    int boff[4]; int bsz[4];
    #pragma unroll
    for (int j = 0; j < 4; j++) {
        int idx = tid + j * 256;
        int row = idx >> 3, seg = idx & 7;
        int p = p0 + row;
        int r = p / 56, c = p - r * 56;
        bool v = (p < HW);
        boff[j] = v ? ((b * PPIX + r * PD + c) * CIN + seg * 8) : 0;
        bsz[j]  = v ? 16 : 0;
    }

    float acc[2][8][4];
    #pragma unroll
    for (int mf = 0; mf < 2; mf++)
        #pragma unroll
        for (int j = 0; j < 8; j++)
            #pragma unroll
            for (int u = 0; u < 4; u++) acc[mf][j][u] = 0.f;

    // ldmatrix lane-address components
    const int aRow = wm * 32 + (lane & 15);
    const int aKb  = (lane >> 4) * 16;
    const int bRow = wn * 64 + ((lane >> 4) << 3) + (lane & 7);
    const int bKb  = ((lane >> 3) & 1) * 16;

    // ---- chunk loader
    auto load_chunk = [&](int ch) {
        int k = ch >> 1, cic = ch & 1;
        int kh = k / 3, kw = k - kh * 3;
        uint32_t buf = ab + (uint32_t)(ch & 1) * BUF_B;
        size_t aslab = (((size_t)b * 9 + k) * 2 + cic) * ((size_t)COUT * 64)
                     + (size_t)cotile * 128 * 64;
        const uint4* pAh = (const uint4*)(g_whi + aslab);
        const uint4* pAl = (const uint4*)(g_wlo + aslab);
        int tap = (kh * PD + kw) * CIN + cic * 64;
        #pragma unroll
        for (int j = 0; j < 4; j++) {
            int idx = tid + j * 256;
            uint32_t so = SW128(idx * 16);
            cp16(buf + so,              pAh + idx, 16);
            cp16(buf + TILE_B + so,     pAl + idx, 16);
            const char* srcBh = (const char*)(g_xhi + boff[j] + tap);
            const char* srcBl = (const char*)(g_xlo + boff[j] + tap);
            cp16(buf + 2 * TILE_B + so, srcBh, bsz[j]);
            cp16(buf + 3 * TILE_B + so, srcBl, bsz[j]);
        }
    };

    load_chunk(0);
    CP_COMMIT();

    for (int ch = 0; ch < 18; ch++) {
        if (ch + 1 < 18) {
            load_chunk(ch + 1);
            CP_COMMIT();
            CP_WAIT(1);
        } else {
            CP_WAIT(0);
        }
        __syncthreads();

        uint32_t buf = ab + (uint32_t)(ch & 1) * BUF_B;
        uint32_t ahB = buf, alB = buf + TILE_B;
        uint32_t bhB = buf + 2 * TILE_B, blB = buf + 3 * TILE_B;

        #pragma unroll
        for (int s = 0; s < 4; s++) {
            int ks = s * 32;
            uint32_t ah[2][4], al[2][4];
            #pragma unroll
            for (int mf = 0; mf < 2; mf++) {
                uint32_t off = SW128((aRow + mf * 16) * 128 + ks + aKb);
                LDSM4(ah[mf], ahB + off);
                LDSM4(al[mf], alB + off);
            }
            uint32_t bh[4][4], bl[4][4];
            #pragma unroll
            for (int nf = 0; nf < 4; nf++) {
                uint32_t off = SW128((bRow + nf * 16) * 128 + ks + bKb);
                LDSM4(bh[nf], bhB + off);
                LDSM4(bl[nf], blB + off);
            }
            #pragma unroll
            for (int mf = 0; mf < 2; mf++)
                #pragma unroll
                for (int nf = 0; nf < 4; nf++) {
                    mma16816(acc[mf][nf * 2],     ah[mf], bh[nf][0], bh[nf][1]);
                    mma16816(acc[mf][nf * 2 + 1], ah[mf], bh[nf][2], bh[nf][3]);
                    mma16816(acc[mf][nf * 2],     ah[mf], bl[nf][0], bl[nf][1]);
                    mma16816(acc[mf][nf * 2 + 1], ah[mf], bl[nf][2], bl[nf][3]);
                    mma16816(acc[mf][nf * 2],     al[mf], bh[nf][0], bh[nf][1]);
                    mma16816(acc[mf][nf * 2 + 1], al[mf], bh[nf][2], bh[nf][3]);
                }
        }
        __syncthreads();
    }

    // ---- epilogue: stage through smem (128 x 132 f32), coalesced stores
    float* sout = (float*)mem;
    const int grp = lane >> 2, tg = lane & 3;
    #pragma unroll
    for (int mf = 0; mf < 2; mf++)
        #pragma unroll
        for (int j = 0; j < 8; j++) {
            int co_l = wm * 32 + mf * 16 + grp;
            int px_l = wn * 64 + j * 8 + tg * 2;
            sout[co_l * 132 + px_l]           = acc[mf][j][0];
            sout[co_l * 132 + px_l + 1]       = acc[mf][j][1];
            sout[(co_l + 8) * 132 + px_l]     = acc[mf][j][2];
            sout[(co_l + 8) * 132 + px_l + 1] = acc[mf][j][3];
        }
    __syncthreads();

    #pragma unroll
    for (int j = 0; j < 16; j++) {
        int idx = tid + j * 256;          // 4096 float4 units
        int row = idx >> 5, u = idx & 31;
        int px = u * 4;
        if (p0 + px + 3 < HW) {
            float4 v = *(float4*)(sout + row * 132 + px);
            float* dst = out + ((size_t)(b * COUT + cotile * 128 + row)) * HW + p0 + px;
            *(float4*)dst = v;
        }
    }
}

// ---------------------------------------------------------------------------
extern "C" void kernel_launch(void* const* d_in, const int* in_sizes, int n_in,
                              void* d_out, int out_size) {
    const float* x     = (const float*)d_in[0];
    const float* convs = (const float*)d_in[1];
    const float* w1    = (const float*)d_in[2];
    const float* b1    = (const float*)d_in[3];
    const float* w2    = (const float*)d_in[4];
    const float* b2    = (const float*)d_in[5];
    float* out = (float*)d_out;
    (void)in_sizes; (void)n_in; (void)out_size;

    cudaFuncSetAttribute(gemm_kernel,
                         cudaFuncAttributeMaxDynamicSharedMemorySize, SMEM_DYN);

    gap_kernel<<<dim3(CIN, B_), 128>>>(x);
    router_kernel<<<B_, 32>>>(w1, b1, w2, b2);
    wmix_kernel<<<COUT, 288>>>(convs);
    xsplit_kernel<<<dim3(98, B_), 256>>>(x);
    xborder_kernel<<<B_, 256>>>();

    gemm_kernel<<<dim3(NTILES, 2, B_), 256, SMEM_DYN>>>(out);
}

// round 7
// speedup vs baseline: 3.8888x; 1.4290x over previous
#include <cuda_runtime.h>
#include <cuda_fp16.h>
#include <cstdint>

// ---------------- problem constants ----------------
#define B_    32
#define CIN   128
#define COUT  256
#define HW    3136
#define HDIM  56
#define PD    58
#define PPIX  (PD*PD)     // 3364
#define EXP_  4
#define RDIM  16
#define NT    128
#define NTILES 25

// ---------------- device scratch ----------------
__device__ float g_routing[B_ * EXP_];
__device__ float g_gap[B_ * CIN];
// W split fp16, GEMM layout: [b][k(9)][cic(2)][co(256)][cii(64)]
__device__ __align__(16) __half g_wh[(size_t)B_ * 9 * 2 * COUT * 64];
__device__ __align__(16) __half g_wl[(size_t)B_ * 9 * 2 * COUT * 64];
// X fp16, padded channel-last: [b][pp(3364)][ci(128)]
__device__ __align__(16) __half g_xh[(size_t)B_ * PPIX * CIN];

// ---------------- helpers ----------------
__device__ __forceinline__ uint32_t smem_u32(const void* p) {
    uint32_t a;
    asm("{ .reg .u64 t; cvta.to.shared.u64 t, %1; cvt.u32.u64 %0, t; }" : "=r"(a) : "l"(p));
    return a;
}
#define SW128(o) ((uint32_t)(o) ^ ((((uint32_t)(o)) >> 3) & 0x70))

__device__ __forceinline__ void cp16(uint32_t dst, const void* src, int sz) {
    asm volatile("cp.async.cg.shared.global [%0], [%1], 16, %2;"
                 :: "r"(dst), "l"(src), "r"(sz) : "memory");
}
#define CP_COMMIT() asm volatile("cp.async.commit_group;" ::: "memory")
#define CP_WAIT(n)  asm volatile("cp.async.wait_group %0;" :: "n"(n) : "memory")

#define LDSM4(r, a)                                                              \
    asm volatile("ldmatrix.sync.aligned.m8n8.x4.shared.b16 {%0,%1,%2,%3}, [%4];" \
        : "=r"((r)[0]), "=r"((r)[1]), "=r"((r)[2]), "=r"((r)[3]) : "r"(a))

__device__ __forceinline__ void mma16816(float* c, const uint32_t* a,
                                         uint32_t b0, uint32_t b1) {
    asm volatile(
        "mma.sync.aligned.m16n8k16.row.col.f32.f16.f16.f32 "
        "{%0,%1,%2,%3}, {%4,%5,%6,%7}, {%8,%9}, {%0,%1,%2,%3};"
        : "+f"(c[0]), "+f"(c[1]), "+f"(c[2]), "+f"(c[3])
        : "r"(a[0]), "r"(a[1]), "r"(a[2]), "r"(a[3]), "r"(b0), "r"(b1));
}

// ---------------------------------------------------------------------------
// Kernel 1a: global average pool.  grid (128, 32), 128 threads.
// ---------------------------------------------------------------------------
__global__ void gap_kernel(const float* __restrict__ x) {
    int c = blockIdx.x, b = blockIdx.y;
    const float* p = x + ((size_t)(b * CIN + c)) * HW;
    float s = 0.f;
    for (int i = threadIdx.x; i < HW; i += 128) s += p[i];
    #pragma unroll
    for (int o = 16; o; o >>= 1) s += __shfl_xor_sync(0xffffffffu, s, o);
    __shared__ float ws[4];
    int wid = threadIdx.x >> 5;
    if ((threadIdx.x & 31) == 0) ws[wid] = s;
    __syncthreads();
    if (threadIdx.x == 0)
        g_gap[b * CIN + c] = (ws[0] + ws[1] + ws[2] + ws[3]) * (1.0f / (float)HW);
}

// ---------------------------------------------------------------------------
// Kernel 1b: router MLP + softmax.  grid 32, 32 threads.
// ---------------------------------------------------------------------------
__global__ void router_kernel(const float* __restrict__ w1, const float* __restrict__ b1,
                              const float* __restrict__ w2, const float* __restrict__ b2) {
    int b = blockIdx.x, t = threadIdx.x;
    __shared__ float h[RDIM], lg[EXP_];
    if (t < RDIM) {
        float a = b1[t];
        const float* wr = w1 + t * CIN;
        const float* gp = g_gap + b * CIN;
        #pragma unroll 8
        for (int c = 0; c < CIN; c++) a = fmaf(wr[c], gp[c], a);
        h[t] = fmaxf(a, 0.f);
    }
    __syncwarp();
    if (t < EXP_) {
        float a = b2[t];
        #pragma unroll
        for (int r = 0; r < RDIM; r++) a = fmaf(w2[t * RDIM + r], h[r], a);
        lg[t] = a;
    }
    __syncwarp();
    if (t == 0) {
        float m = fmaxf(fmaxf(lg[0], lg[1]), fmaxf(lg[2], lg[3]));
        float e[EXP_], ss = 0.f;
        #pragma unroll
        for (int i = 0; i < EXP_; i++) { e[i] = expf((lg[i] - m) * (1.0f / 30.0f)); ss += e[i]; }
        float inv = 1.0f / ss;
        #pragma unroll
        for (int i = 0; i < EXP_; i++) g_routing[b * EXP_ + i] = e[i] * inv;
    }
}

// ---------------------------------------------------------------------------
// Kernel 2: mix experts + hi/lo fp16 split of W, GEMM tile layout.
// ---------------------------------------------------------------------------
__global__ void wmix_kernel(const float* __restrict__ convs) {
    int co = blockIdx.x;
    int tid = threadIdx.x;
    __shared__ float se[EXP_][CIN * 9];
    for (int e = 0; e < EXP_; e++) {
        const float* src = convs + ((size_t)(e * COUT + co)) * (CIN * 9);
        for (int i = tid; i < CIN * 9; i += 288) se[e][i] = src[i];
    }
    __syncthreads();
    for (int b = 0; b < B_; b++) {
        float r0 = g_routing[b * EXP_ + 0], r1 = g_routing[b * EXP_ + 1];
        float r2 = g_routing[b * EXP_ + 2], r3 = g_routing[b * EXP_ + 3];
        #pragma unroll
        for (int it = 0; it < 4; it++) {
            int idx = it * 288 + tid;
            int k = idx >> 7;
            int ci = idx & 127;
            int j = ci * 9 + k;
            float v = fmaf(r0, se[0][j], fmaf(r1, se[1][j], fmaf(r2, se[2][j], r3 * se[3][j])));
            __half hi = __float2half_rn(v);
            __half lo = __float2half_rn(v - __half2float(hi));
            size_t d = ((((size_t)b * 9 + k) * 2 + (ci >> 6)) * COUT + co) * 64 + (ci & 63);
            g_wh[d] = hi;
            g_wl[d] = lo;
        }
    }
}

// ---------------------------------------------------------------------------
// Kernel 3a: transpose x -> padded channel-last fp16 (interior only).
// ---------------------------------------------------------------------------
__global__ void xsplit_kernel(const float* __restrict__ x) {
    __shared__ float s[CIN][33];
    int p0 = blockIdx.x * 32, b = blockIdx.y;
    int tid = threadIdx.x, lane = tid & 31, grp8 = tid >> 5;
    #pragma unroll 4
    for (int pass = 0; pass < 16; pass++) {
        int ci = pass * 8 + grp8;
        s[ci][lane] = x[((size_t)(b * CIN + ci)) * HW + p0 + lane];
    }
    __syncthreads();
    int pl = tid >> 3, g = tid & 7;
    int p = p0 + pl;
    int r = p / 56, c = p - r * 56;
    int pp = (r + 1) * PD + (c + 1);
    size_t base = ((size_t)(b * PPIX + pp)) * CIN + g * 16;
    __half hv[16];
    #pragma unroll
    for (int u = 0; u < 16; u++) hv[u] = __float2half_rn(s[g * 16 + u][pl]);
    *(uint4*)(g_xh + base)     = *(uint4*)(hv);
    *(uint4*)(g_xh + base + 8) = *(uint4*)(hv + 8);
}

// Kernel 3b: zero border pixels.
__global__ void xborder_kernel() {
    int b = blockIdx.x;
    uint4 z = {0, 0, 0, 0};
    for (int idx = threadIdx.x; idx < 228 * 16; idx += 256) {
        int i = idx >> 4, u = idx & 15;
        int pp;
        if (i < 58)       pp = i;
        else if (i < 116) pp = 57 * PD + (i - 58);
        else { int j = i - 116; pp = (1 + (j >> 1)) * PD + (j & 1) * 57; }
        size_t base = ((size_t)(b * PPIX + pp)) * CIN;
        ((uint4*)(g_xh + base))[u] = z;
    }
}

// ---------------------------------------------------------------------------
// Kernel 4: fp16x2-split implicit-GEMM conv with tap-resident B.
// grid (25, 2, 32), 256 threads (8 warps).  CTA tile 128co x 128px.
// B: 6 padded rows x 58 px x 128 ci fp16 resident in smem (348 px-rows =
//    89KB, loaded once) -- a 128-px tile can span 4 output rows (+2 halo).
//    Taps become row-offset addressing (+kh*58+kw) into the same buffer.
// A: Wh|Wl 16KB tiles per chunk (9 taps x 2 ci halves), cp.async double-buffer.
// MMA terms per chunk: Ah*B + Al*B (2-term fp16 split of W, single-rounded X).
// ---------------------------------------------------------------------------
#define BROWS    348
#define BRES_PAD (BROWS * 256)      // 89088, 1KB multiple
#define ATILE_B  16384
#define SMEM_DYN (BRES_PAD + 4 * ATILE_B + 1024)

__global__ __launch_bounds__(256, 1)
void gemm_kernel(float* __restrict__ out) {
    extern __shared__ char dyn[];
    uint32_t sb = smem_u32(dyn);
    uint32_t ab = (sb + 1023u) & ~1023u;
    char* mem = dyn + (ab - sb);

    const int tid = threadIdx.x, w = tid >> 5, lane = tid & 31;
    const int wm = w & 3, wn = w >> 2;
    const int ntile = blockIdx.x, cotile = blockIdx.y, b = blockIdx.z;
    const int p0 = ntile * NT;
    const int r0 = p0 / 56;

    const uint32_t Bsm = ab;
    const uint32_t Asm = ab + BRES_PAD;

    // ---- B resident fill: 348 pixel rows, [pp][128ci], xor-swizzled 16B units
    for (int t = tid; t < BROWS * 16; t += 256) {
        int lp = t >> 4, u = t & 15;
        int gpp = r0 * 58 + lp;
        bool v = gpp < PPIX;
        uint32_t dst = Bsm + lp * 256 + ((u & 8) << 4) + ((((u & 7) ^ (lp & 7))) << 4);
        const char* src = (const char*)(g_xh + ((size_t)b * PPIX + (v ? gpp : 0)) * CIN + u * 8);
        cp16(dst, src, v ? 16 : 0);
    }

    // ---- A chunk loader (double-buffered)
    auto load_A = [&](int ch) {
        int k = ch >> 1, cic = ch & 1;
        uint32_t buf = Asm + (uint32_t)(ch & 1) * (2 * ATILE_B);
        size_t aslab = (((size_t)b * 9 + k) * 2 + cic) * ((size_t)COUT * 64)
                     + (size_t)cotile * 128 * 64;
        const uint4* pAh = (const uint4*)(g_wh + aslab);
        const uint4* pAl = (const uint4*)(g_wl + aslab);
        #pragma unroll
        for (int j = 0; j < 4; j++) {
            int idx = tid + j * 256;
            uint32_t so = SW128(idx * 16);
            cp16(buf + so,           pAh + idx, 16);
            cp16(buf + ATILE_B + so, pAl + idx, 16);
        }
    };

    // ---- per-thread ldmatrix address components
    const int aRow = wm * 32 + (lane & 15);
    const int aKb  = (lane >> 4) * 16;
    const int jlo  = (lane >> 3) & 1;
    const int rowin = ((lane >> 4) << 3) + (lane & 7);
    int lrB[4];
    #pragma unroll
    for (int nf = 0; nf < 4; nf++) {
        int n = wn * 64 + nf * 16 + rowin;
        int p = p0 + n;
        if (p >= HW) p = HW - 1;           // clamp; results discarded in epilogue
        int r = p / 56, c = p - r * 56;
        lrB[nf] = (r - r0) * 58 + c;       // tap(0,0) local row
    }

    float acc[2][8][4];
    #pragma unroll
    for (int mf = 0; mf < 2; mf++)
        #pragma unroll
        for (int j = 0; j < 8; j++)
            #pragma unroll
            for (int u = 0; u < 4; u++) acc[mf][j][u] = 0.f;

    load_A(0);
    CP_COMMIT();

    for (int ch = 0; ch < 18; ch++) {
        if (ch + 1 < 18) {
            load_A(ch + 1);
            CP_COMMIT();
            CP_WAIT(1);
        } else {
            CP_WAIT(0);
        }
        __syncthreads();

        const int k = ch >> 1, cic = ch & 1;
        const int kh = k / 3, kw = k - kh * 3;
        const int toff = kh * 58 + kw;
        const uint32_t ahB = Asm + (uint32_t)(ch & 1) * (2 * ATILE_B);
        const uint32_t alB = ahB + ATILE_B;
        const uint32_t cicOff = Bsm + cic * 128;

        #pragma unroll
        for (int s = 0; s < 4; s++) {
            const int ks = s * 32;
            uint32_t ah[2][4], al[2][4];
            #pragma unroll
            for (int mf = 0; mf < 2; mf++) {
                uint32_t off = SW128((aRow + mf * 16) * 128 + ks + aKb);
                LDSM4(ah[mf], ahB + off);
                LDSM4(al[mf], alB + off);
            }
            uint32_t bh[4][4];
            #pragma unroll
            for (int nf = 0; nf < 4; nf++) {
                int lr = lrB[nf] + toff;
                uint32_t addr = cicOff + lr * 256 + ((((s << 1) | jlo) ^ (lr & 7)) << 4);
                LDSM4(bh[nf], addr);
            }
            #pragma unroll
            for (int mf = 0; mf < 2; mf++)
                #pragma unroll
                for (int nf = 0; nf < 4; nf++) {
                    mma16816(acc[mf][nf * 2],     ah[mf], bh[nf][0], bh[nf][1]);
                    mma16816(acc[mf][nf * 2 + 1], ah[mf], bh[nf][2], bh[nf][3]);
                    mma16816(acc[mf][nf * 2],     al[mf], bh[nf][0], bh[nf][1]);
                    mma16816(acc[mf][nf * 2 + 1], al[mf], bh[nf][2], bh[nf][3]);
                }
        }
        __syncthreads();
    }

    // ---- epilogue: stage through smem, coalesced float4 stores
    float* sout = (float*)mem;
    const int grp = lane >> 2, tg = lane & 3;
    #pragma unroll
    for (int mf = 0; mf < 2; mf++)
        #pragma unroll
        for (int j = 0; j < 8; j++) {
            int co_l = wm * 32 + mf * 16 + grp;
            int px_l = wn * 64 + j * 8 + tg * 2;
            sout[co_l * 132 + px_l]           = acc[mf][j][0];
            sout[co_l * 132 + px_l + 1]       = acc[mf][j][1];
            sout[(co_l + 8) * 132 + px_l]     = acc[mf][j][2];
            sout[(co_l + 8) * 132 + px_l + 1] = acc[mf][j][3];
        }
    __syncthreads();

    #pragma unroll
    for (int j = 0; j < 16; j++) {
        int idx = tid + j * 256;
        int row = idx >> 5, u = idx & 31;
        int px = u * 4;
        if (p0 + px + 3 < HW) {
            float4 v = *(float4*)(sout + row * 132 + px);
            float* dst = out + ((size_t)(b * COUT + cotile * 128 + row)) * HW + p0 + px;
            *(float4*)dst = v;
        }
    }
}

// ---------------------------------------------------------------------------
extern "C" void kernel_launch(void* const* d_in, const int* in_sizes, int n_in,
                              void* d_out, int out_size) {
    const float* x     = (const float*)d_in[0];
    const float* convs = (const float*)d_in[1];
    const float* w1    = (const float*)d_in[2];
    const float* b1    = (const float*)d_in[3];
    const float* w2    = (const float*)d_in[4];
    const float* b2    = (const float*)d_in[5];
    float* out = (float*)d_out;
    (void)in_sizes; (void)n_in; (void)out_size;

    cudaFuncSetAttribute(gemm_kernel,
                         cudaFuncAttributeMaxDynamicSharedMemorySize, SMEM_DYN);

    gap_kernel<<<dim3(CIN, B_), 128>>>(x);
    router_kernel<<<B_, 32>>>(w1, b1, w2, b2);
    wmix_kernel<<<COUT, 288>>>(convs);
    xsplit_kernel<<<dim3(98, B_), 256>>>(x);
    xborder_kernel<<<B_, 256>>>();

    gemm_kernel<<<dim3(NTILES, 2, B_), 256, SMEM_DYN>>>(out);
}

// round 8
// speedup vs baseline: 5.5771x; 1.4342x over previous
#include <cuda_runtime.h>
#include <cuda_fp16.h>
#include <cstdint>

// ---------------- problem constants ----------------
#define B_    32
#define CIN   128
#define COUT  256
#define HW    3136
#define HDIM  56
#define PD    58
#define PPIX  (PD*PD)     // 3364
#define EXP_  4
#define RDIM  16
#define NT    128
#define NTILES 25

// ---------------- device scratch ----------------
__device__ float g_routing[B_ * EXP_];
__device__ float g_gap[B_ * CIN];
// W fp16 (single-rounded), GEMM layout: [b][k(9)][cic(2)][co(256)][cii(64)]
__device__ __align__(16) __half g_wh[(size_t)B_ * 9 * 2 * COUT * 64];
// X fp16, padded channel-last: [b][pp(3364)][ci(128)]
__device__ __align__(16) __half g_xh[(size_t)B_ * PPIX * CIN];

// ---------------- helpers ----------------
__device__ __forceinline__ uint32_t smem_u32(const void* p) {
    uint32_t a;
    asm("{ .reg .u64 t; cvta.to.shared.u64 t, %1; cvt.u32.u64 %0, t; }" : "=r"(a) : "l"(p));
    return a;
}
#define SW128(o) ((uint32_t)(o) ^ ((((uint32_t)(o)) >> 3) & 0x70))

__device__ __forceinline__ void cp16(uint32_t dst, const void* src, int sz) {
    asm volatile("cp.async.cg.shared.global [%0], [%1], 16, %2;"
                 :: "r"(dst), "l"(src), "r"(sz) : "memory");
}
#define CP_COMMIT() asm volatile("cp.async.commit_group;" ::: "memory")
#define CP_WAIT(n)  asm volatile("cp.async.wait_group %0;" :: "n"(n) : "memory")

#define LDSM4(r, a)                                                              \
    asm volatile("ldmatrix.sync.aligned.m8n8.x4.shared.b16 {%0,%1,%2,%3}, [%4];" \
        : "=r"((r)[0]), "=r"((r)[1]), "=r"((r)[2]), "=r"((r)[3]) : "r"(a))

__device__ __forceinline__ void mma16816(float* c, const uint32_t* a,
                                         uint32_t b0, uint32_t b1) {
    asm volatile(
        "mma.sync.aligned.m16n8k16.row.col.f32.f16.f16.f32 "
        "{%0,%1,%2,%3}, {%4,%5,%6,%7}, {%8,%9}, {%0,%1,%2,%3};"
        : "+f"(c[0]), "+f"(c[1]), "+f"(c[2]), "+f"(c[3])
        : "r"(a[0]), "r"(a[1]), "r"(a[2]), "r"(a[3]), "r"(b0), "r"(b1));
}

// ---------------------------------------------------------------------------
// Kernel 1a: global average pool.  grid (128, 32), 128 threads.
// ---------------------------------------------------------------------------
__global__ void gap_kernel(const float* __restrict__ x) {
    int c = blockIdx.x, b = blockIdx.y;
    const float* p = x + ((size_t)(b * CIN + c)) * HW;
    float s = 0.f;
    for (int i = threadIdx.x; i < HW; i += 128) s += p[i];
    #pragma unroll
    for (int o = 16; o; o >>= 1) s += __shfl_xor_sync(0xffffffffu, s, o);
    __shared__ float ws[4];
    int wid = threadIdx.x >> 5;
    if ((threadIdx.x & 31) == 0) ws[wid] = s;
    __syncthreads();
    if (threadIdx.x == 0)
        g_gap[b * CIN + c] = (ws[0] + ws[1] + ws[2] + ws[3]) * (1.0f / (float)HW);
}

// ---------------------------------------------------------------------------
// Kernel 1b: router MLP + softmax.  grid 32, 32 threads.
// ---------------------------------------------------------------------------
__global__ void router_kernel(const float* __restrict__ w1, const float* __restrict__ b1,
                              const float* __restrict__ w2, const float* __restrict__ b2) {
    int b = blockIdx.x, t = threadIdx.x;
    __shared__ float h[RDIM], lg[EXP_];
    if (t < RDIM) {
        float a = b1[t];
        const float* wr = w1 + t * CIN;
        const float* gp = g_gap + b * CIN;
        #pragma unroll 8
        for (int c = 0; c < CIN; c++) a = fmaf(wr[c], gp[c], a);
        h[t] = fmaxf(a, 0.f);
    }
    __syncwarp();
    if (t < EXP_) {
        float a = b2[t];
        #pragma unroll
        for (int r = 0; r < RDIM; r++) a = fmaf(w2[t * RDIM + r], h[r], a);
        lg[t] = a;
    }
    __syncwarp();
    if (t == 0) {
        float m = fmaxf(fmaxf(lg[0], lg[1]), fmaxf(lg[2], lg[3]));
        float e[EXP_], ss = 0.f;
        #pragma unroll
        for (int i = 0; i < EXP_; i++) { e[i] = expf((lg[i] - m) * (1.0f / 30.0f)); ss += e[i]; }
        float inv = 1.0f / ss;
        #pragma unroll
        for (int i = 0; i < EXP_; i++) g_routing[b * EXP_ + i] = e[i] * inv;
    }
}

// ---------------------------------------------------------------------------
// Kernel 2: mix experts -> fp16 W, GEMM tile layout.
// ---------------------------------------------------------------------------
__global__ void wmix_kernel(const float* __restrict__ convs) {
    int co = blockIdx.x;
    int tid = threadIdx.x;
    __shared__ float se[EXP_][CIN * 9];
    for (int e = 0; e < EXP_; e++) {
        const float* src = convs + ((size_t)(e * COUT + co)) * (CIN * 9);
        for (int i = tid; i < CIN * 9; i += 288) se[e][i] = src[i];
    }
    __syncthreads();
    for (int b = 0; b < B_; b++) {
        float r0 = g_routing[b * EXP_ + 0], r1 = g_routing[b * EXP_ + 1];
        float r2 = g_routing[b * EXP_ + 2], r3 = g_routing[b * EXP_ + 3];
        #pragma unroll
        for (int it = 0; it < 4; it++) {
            int idx = it * 288 + tid;
            int k = idx >> 7;
            int ci = idx & 127;
            int j = ci * 9 + k;
            float v = fmaf(r0, se[0][j], fmaf(r1, se[1][j], fmaf(r2, se[2][j], r3 * se[3][j])));
            size_t d = ((((size_t)b * 9 + k) * 2 + (ci >> 6)) * COUT + co) * 64 + (ci & 63);
            g_wh[d] = __float2half_rn(v);
        }
    }
}

// ---------------------------------------------------------------------------
// Kernel 3a: transpose x -> padded channel-last fp16 (interior only).
// ---------------------------------------------------------------------------
__global__ void xsplit_kernel(const float* __restrict__ x) {
    __shared__ float s[CIN][33];
    int p0 = blockIdx.x * 32, b = blockIdx.y;
    int tid = threadIdx.x, lane = tid & 31, grp8 = tid >> 5;
    #pragma unroll 4
    for (int pass = 0; pass < 16; pass++) {
        int ci = pass * 8 + grp8;
        s[ci][lane] = x[((size_t)(b * CIN + ci)) * HW + p0 + lane];
    }
    __syncthreads();
    int pl = tid >> 3, g = tid & 7;
    int p = p0 + pl;
    int r = p / 56, c = p - r * 56;
    int pp = (r + 1) * PD + (c + 1);
    size_t base = ((size_t)(b * PPIX + pp)) * CIN + g * 16;
    __half hv[16];
    #pragma unroll
    for (int u = 0; u < 16; u++) hv[u] = __float2half_rn(s[g * 16 + u][pl]);
    *(uint4*)(g_xh + base)     = *(uint4*)(hv);
    *(uint4*)(g_xh + base + 8) = *(uint4*)(hv + 8);
}

// Kernel 3b: zero border pixels.
__global__ void xborder_kernel() {
    int b = blockIdx.x;
    uint4 z = {0, 0, 0, 0};
    for (int idx = threadIdx.x; idx < 228 * 16; idx += 256) {
        int i = idx >> 4, u = idx & 15;
        int pp;
        if (i < 58)       pp = i;
        else if (i < 116) pp = 57 * PD + (i - 58);
        else { int j = i - 116; pp = (1 + (j >> 1)) * PD + (j & 1) * 57; }
        size_t base = ((size_t)(b * PPIX + pp)) * CIN;
        ((uint4*)(g_xh + base))[u] = z;
    }
}

// ---------------------------------------------------------------------------
// Kernel 4: single-term fp16 implicit-GEMM conv with tap-resident B.
// grid (25, 2, 32), 256 threads (8 warps).  CTA tile 128co x 128px.
// B: 6 padded rows x 58 px x 128 ci fp16 resident in smem (348 px-rows, 89KB),
//    loaded once; taps are row offsets (+kh*58+kw) into the same buffer.
// A: W 16KB tile per chunk (9 taps x 2 ci halves), cp.async double-buffered.
// ---------------------------------------------------------------------------
#define BROWS    348
#define BRES_PAD (BROWS * 256)      // 89088
#define ATILE_B  16384
#define SMEM_DYN (BRES_PAD + 2 * ATILE_B + 1024)

__global__ __launch_bounds__(256, 1)
void gemm_kernel(float* __restrict__ out) {
    extern __shared__ char dyn[];
    uint32_t sb = smem_u32(dyn);
    uint32_t ab = (sb + 1023u) & ~1023u;
    char* mem = dyn + (ab - sb);

    const int tid = threadIdx.x, w = tid >> 5, lane = tid & 31;
    const int wm = w & 3, wn = w >> 2;
    const int ntile = blockIdx.x, cotile = blockIdx.y, b = blockIdx.z;
    const int p0 = ntile * NT;
    const int r0 = p0 / 56;

    const uint32_t Bsm = ab;
    const uint32_t Asm = ab + BRES_PAD;

    // ---- B resident fill: 348 pixel rows, [pp][128ci], xor-swizzled 16B units
    for (int t = tid; t < BROWS * 16; t += 256) {
        int lp = t >> 4, u = t & 15;
        int gpp = r0 * 58 + lp;
        bool v = gpp < PPIX;
        uint32_t dst = Bsm + lp * 256 + ((u & 8) << 4) + ((((u & 7) ^ (lp & 7))) << 4);
        const char* src = (const char*)(g_xh + ((size_t)b * PPIX + (v ? gpp : 0)) * CIN + u * 8);
        cp16(dst, src, v ? 16 : 0);
    }

    // ---- A chunk loader (double-buffered, 16KB per chunk)
    auto load_A = [&](int ch) {
        int k = ch >> 1, cic = ch & 1;
        uint32_t buf = Asm + (uint32_t)(ch & 1) * ATILE_B;
        size_t aslab = (((size_t)b * 9 + k) * 2 + cic) * ((size_t)COUT * 64)
                     + (size_t)cotile * 128 * 64;
        const uint4* pAh = (const uint4*)(g_wh + aslab);
        #pragma unroll
        for (int j = 0; j < 4; j++) {
            int idx = tid + j * 256;
            uint32_t so = SW128(idx * 16);
            cp16(buf + so, pAh + idx, 16);
        }
    };

    // ---- per-thread ldmatrix address components
    const int aRow = wm * 32 + (lane & 15);
    const int aKb  = (lane >> 4) * 16;
    const int jlo  = (lane >> 3) & 1;
    const int rowin = ((lane >> 4) << 3) + (lane & 7);
    int lrB[4];
    #pragma unroll
    for (int nf = 0; nf < 4; nf++) {
        int n = wn * 64 + nf * 16 + rowin;
        int p = p0 + n;
        if (p >= HW) p = HW - 1;           // clamp; results discarded in epilogue
        int r = p / 56, c = p - r * 56;
        lrB[nf] = (r - r0) * 58 + c;       // tap(0,0) local row
    }

    float acc[2][8][4];
    #pragma unroll
    for (int mf = 0; mf < 2; mf++)
        #pragma unroll
        for (int j = 0; j < 8; j++)
            #pragma unroll
            for (int u = 0; u < 4; u++) acc[mf][j][u] = 0.f;

    load_A(0);
    CP_COMMIT();

    for (int ch = 0; ch < 18; ch++) {
        if (ch + 1 < 18) {
            load_A(ch + 1);
            CP_COMMIT();
            CP_WAIT(1);
        } else {
            CP_WAIT(0);
        }
        __syncthreads();

        const int k = ch >> 1, cic = ch & 1;
        const int kh = k / 3, kw = k - kh * 3;
        const int toff = kh * 58 + kw;
        const uint32_t ahB = Asm + (uint32_t)(ch & 1) * ATILE_B;
        const uint32_t cicOff = Bsm + cic * 128;

        #pragma unroll
        for (int s = 0; s < 4; s++) {
            const int ks = s * 32;
            uint32_t ah[2][4];
            #pragma unroll
            for (int mf = 0; mf < 2; mf++) {
                uint32_t off = SW128((aRow + mf * 16) * 128 + ks + aKb);
                LDSM4(ah[mf], ahB + off);
            }
            uint32_t bh[4][4];
            #pragma unroll
            for (int nf = 0; nf < 4; nf++) {
                int lr = lrB[nf] + toff;
                uint32_t addr = cicOff + lr * 256 + ((((s << 1) | jlo) ^ (lr & 7)) << 4);
                LDSM4(bh[nf], addr);
            }
            #pragma unroll
            for (int mf = 0; mf < 2; mf++)
                #pragma unroll
                for (int nf = 0; nf < 4; nf++) {
                    mma16816(acc[mf][nf * 2],     ah[mf], bh[nf][0], bh[nf][1]);
                    mma16816(acc[mf][nf * 2 + 1], ah[mf], bh[nf][2], bh[nf][3]);
                }
        }
        __syncthreads();
    }

    // ---- epilogue: stage through smem, coalesced float4 stores
    float* sout = (float*)mem;
    const int grp = lane >> 2, tg = lane & 3;
    #pragma unroll
    for (int mf = 0; mf < 2; mf++)
        #pragma unroll
        for (int j = 0; j < 8; j++) {
            int co_l = wm * 32 + mf * 16 + grp;
            int px_l = wn * 64 + j * 8 + tg * 2;
            sout[co_l * 132 + px_l]           = acc[mf][j][0];
            sout[co_l * 132 + px_l + 1]       = acc[mf][j][1];
            sout[(co_l + 8) * 132 + px_l]     = acc[mf][j][2];
            sout[(co_l + 8) * 132 + px_l + 1] = acc[mf][j][3];
        }
    __syncthreads();

    #pragma unroll
    for (int j = 0; j < 16; j++) {
        int idx = tid + j * 256;
        int row = idx >> 5, u = idx & 31;
        int px = u * 4;
        if (p0 + px + 3 < HW) {
            float4 v = *(float4*)(sout + row * 132 + px);
            float* dst = out + ((size_t)(b * COUT + cotile * 128 + row)) * HW + p0 + px;
            *(float4*)dst = v;
        }
    }
}

// ---------------------------------------------------------------------------
extern "C" void kernel_launch(void* const* d_in, const int* in_sizes, int n_in,
                              void* d_out, int out_size) {
    const float* x     = (const float*)d_in[0];
    const float* convs = (const float*)d_in[1];
    const float* w1    = (const float*)d_in[2];
    const float* b1    = (const float*)d_in[3];
    const float* w2    = (const float*)d_in[4];
    const float* b2    = (const float*)d_in[5];
    float* out = (float*)d_out;
    (void)in_sizes; (void)n_in; (void)out_size;

    cudaFuncSetAttribute(gemm_kernel,
                         cudaFuncAttributeMaxDynamicSharedMemorySize, SMEM_DYN);

    gap_kernel<<<dim3(CIN, B_), 128>>>(x);
    router_kernel<<<B_, 32>>>(w1, b1, w2, b2);
    wmix_kernel<<<COUT, 288>>>(convs);
    xsplit_kernel<<<dim3(98, B_), 256>>>(x);
    xborder_kernel<<<B_, 256>>>();

    gemm_kernel<<<dim3(NTILES, 2, B_), 256, SMEM_DYN>>>(out);
}

// round 9
// speedup vs baseline: 5.6532x; 1.0137x over previous
#include <cuda_runtime.h>
#include <cuda_fp16.h>
#include <cstdint>

// ---------------- problem constants ----------------
#define B_    32
#define CIN   128
#define COUT  256
#define HW    3136
#define HDIM  56
#define PD    58
#define PPIX  (PD*PD)     // 3364
#define EXP_  4
#define RDIM  16
#define NT    128
#define NTILES 25

// ---------------- device scratch ----------------
__device__ float g_routing[B_ * EXP_];
__device__ float g_gap[B_ * CIN];     // raw channel sums (scaled in router)
// W fp16, GEMM layout: [b][k(9)][cic(2)][co(256)][cii(64)]
__device__ __align__(16) __half g_wh[(size_t)B_ * 9 * 2 * COUT * 64];
// X fp16, padded channel-last: [b][pp(3364)][ci(128)]
__device__ __align__(16) __half g_xh[(size_t)B_ * PPIX * CIN];

// ---------------- helpers ----------------
__device__ __forceinline__ uint32_t smem_u32(const void* p) {
    uint32_t a;
    asm("{ .reg .u64 t; cvta.to.shared.u64 t, %1; cvt.u32.u64 %0, t; }" : "=r"(a) : "l"(p));
    return a;
}
#define SW128(o) ((uint32_t)(o) ^ ((((uint32_t)(o)) >> 3) & 0x70))

__device__ __forceinline__ void cp16(uint32_t dst, const void* src, int sz) {
    asm volatile("cp.async.cg.shared.global [%0], [%1], 16, %2;"
                 :: "r"(dst), "l"(src), "r"(sz) : "memory");
}
#define CP_COMMIT() asm volatile("cp.async.commit_group;" ::: "memory")
#define CP_WAIT(n)  asm volatile("cp.async.wait_group %0;" :: "n"(n) : "memory")

#define LDSM4(r, a)                                                              \
    asm volatile("ldmatrix.sync.aligned.m8n8.x4.shared.b16 {%0,%1,%2,%3}, [%4];" \
        : "=r"((r)[0]), "=r"((r)[1]), "=r"((r)[2]), "=r"((r)[3]) : "r"(a))

__device__ __forceinline__ void mma16816(float* c, const uint32_t* a,
                                         uint32_t b0, uint32_t b1) {
    asm volatile(
        "mma.sync.aligned.m16n8k16.row.col.f32.f16.f16.f32 "
        "{%0,%1,%2,%3}, {%4,%5,%6,%7}, {%8,%9}, {%0,%1,%2,%3};"
        : "+f"(c[0]), "+f"(c[1]), "+f"(c[2]), "+f"(c[3])
        : "r"(a[0]), "r"(a[1]), "r"(a[2]), "r"(a[3]), "r"(b0), "r"(b1));
}

// ---------------------------------------------------------------------------
// Kernel A (runs FIRST): zero border pixels of padded X and zero g_gap.
// ---------------------------------------------------------------------------
__global__ void xborder_kernel() {
    int b = blockIdx.x;
    if (threadIdx.x < CIN) g_gap[b * CIN + threadIdx.x] = 0.f;
    uint4 z = {0, 0, 0, 0};
    for (int idx = threadIdx.x; idx < 228 * 16; idx += 256) {
        int i = idx >> 4, u = idx & 15;
        int pp;
        if (i < 58)       pp = i;
        else if (i < 116) pp = 57 * PD + (i - 58);
        else { int j = i - 116; pp = (1 + (j >> 1)) * PD + (j & 1) * 57; }
        size_t base = ((size_t)(b * PPIX + pp)) * CIN;
        ((uint4*)(g_xh + base))[u] = z;
    }
}

// ---------------------------------------------------------------------------
// Kernel B: transpose x -> padded channel-last fp16 + fused GAP accumulation.
// grid (98, 32), 256 threads.
// ---------------------------------------------------------------------------
__global__ void xsplit_kernel(const float* __restrict__ x) {
    __shared__ float s[CIN][33];
    int p0 = blockIdx.x * 32, b = blockIdx.y;
    int tid = threadIdx.x, lane = tid & 31, grp8 = tid >> 5;
    #pragma unroll 4
    for (int pass = 0; pass < 16; pass++) {
        int ci = pass * 8 + grp8;
        s[ci][lane] = x[((size_t)(b * CIN + ci)) * HW + p0 + lane];
    }
    __syncthreads();

    // fused GAP partial: threads 0..127 each reduce one channel over 32 px
    if (tid < CIN) {
        float sum = 0.f;
        #pragma unroll 8
        for (int j = 0; j < 32; j++) sum += s[tid][j];
        atomicAdd(&g_gap[b * CIN + tid], sum);
    }

    int pl = tid >> 3, g = tid & 7;
    int p = p0 + pl;
    int r = p / 56, c = p - r * 56;
    int pp = (r + 1) * PD + (c + 1);
    size_t base = ((size_t)(b * PPIX + pp)) * CIN + g * 16;
    __half hv[16];
    #pragma unroll
    for (int u = 0; u < 16; u++) hv[u] = __float2half_rn(s[g * 16 + u][pl]);
    *(uint4*)(g_xh + base)     = *(uint4*)(hv);
    *(uint4*)(g_xh + base + 8) = *(uint4*)(hv + 8);
}

// ---------------------------------------------------------------------------
// Kernel C: router MLP + softmax.  grid 32, 32 threads.  (gap scaled here)
// ---------------------------------------------------------------------------
__global__ void router_kernel(const float* __restrict__ w1, const float* __restrict__ b1,
                              const float* __restrict__ w2, const float* __restrict__ b2) {
    int b = blockIdx.x, t = threadIdx.x;
    __shared__ float h[RDIM], lg[EXP_];
    const float invHW = 1.0f / (float)HW;
    if (t < RDIM) {
        float a = b1[t];
        const float* wr = w1 + t * CIN;
        const float* gp = g_gap + b * CIN;
        #pragma unroll 8
        for (int c = 0; c < CIN; c++) a = fmaf(wr[c], gp[c] * invHW, a);
        h[t] = fmaxf(a, 0.f);
    }
    __syncwarp();
    if (t < EXP_) {
        float a = b2[t];
        #pragma unroll
        for (int r = 0; r < RDIM; r++) a = fmaf(w2[t * RDIM + r], h[r], a);
        lg[t] = a;
    }
    __syncwarp();
    if (t == 0) {
        float m = fmaxf(fmaxf(lg[0], lg[1]), fmaxf(lg[2], lg[3]));
        float e[EXP_], ss = 0.f;
        #pragma unroll
        for (int i = 0; i < EXP_; i++) { e[i] = expf((lg[i] - m) * (1.0f / 30.0f)); ss += e[i]; }
        float inv = 1.0f / ss;
        #pragma unroll
        for (int i = 0; i < EXP_; i++) g_routing[b * EXP_ + i] = e[i] * inv;
    }
}

// ---------------------------------------------------------------------------
// Kernel D: mix experts -> fp16 W, GEMM tile layout, vectorized 8B stores.
// grid 256 (co), 288 threads; each thread owns 4 consecutive cii.
// ---------------------------------------------------------------------------
__global__ void wmix_kernel(const float* __restrict__ convs) {
    int co = blockIdx.x;
    int tid = threadIdx.x;
    __shared__ float se[EXP_][CIN * 9];
    for (int e = 0; e < EXP_; e++) {
        const float* src = convs + ((size_t)(e * COUT + co)) * (CIN * 9);
        for (int i = tid; i < CIN * 9; i += 288) se[e][i] = src[i];
    }
    __syncthreads();

    const int base = tid * 4;            // 288*4 = 1152
    const int k    = base / 128;
    const int rem  = base & 127;
    const int cic  = rem >> 6;
    const int cii  = rem & 63;

    for (int b = 0; b < B_; b++) {
        float r0 = g_routing[b * EXP_ + 0], r1 = g_routing[b * EXP_ + 1];
        float r2 = g_routing[b * EXP_ + 2], r3 = g_routing[b * EXP_ + 3];
        __half hv[4];
        #pragma unroll
        for (int u = 0; u < 4; u++) {
            int ci = cic * 64 + cii + u;
            int j = ci * 9 + k;
            float v = fmaf(r0, se[0][j], fmaf(r1, se[1][j], fmaf(r2, se[2][j], r3 * se[3][j])));
            hv[u] = __float2half_rn(v);
        }
        size_t d = ((((size_t)b * 9 + k) * 2 + cic) * COUT + co) * 64 + cii;
        *(uint2*)(g_wh + d) = *(uint2*)hv;
    }
}

// ---------------------------------------------------------------------------
// Kernel E: single-term fp16 implicit-GEMM conv, tap-resident B, 512 threads.
// grid (25, 2, 32), 16 warps (4x4), warp tile 32co x 32px.
// B: 348 px-rows x 256B resident (89KB); A: 16KB/chunk double-buffered.
// ---------------------------------------------------------------------------
#define BROWS    348
#define BRES_PAD (BROWS * 256)      // 89088
#define ATILE_B  16384
#define SMEM_DYN (BRES_PAD + 2 * ATILE_B + 1024)

__global__ __launch_bounds__(512, 1)
void gemm_kernel(float* __restrict__ out) {
    extern __shared__ char dyn[];
    uint32_t sb = smem_u32(dyn);
    uint32_t ab = (sb + 1023u) & ~1023u;
    char* mem = dyn + (ab - sb);

    const int tid = threadIdx.x, w = tid >> 5, lane = tid & 31;
    const int wm = w & 3, wn = w >> 2;           // 4 x 4 warp grid
    const int ntile = blockIdx.x, cotile = blockIdx.y, b = blockIdx.z;
    const int p0 = ntile * NT;
    const int r0 = p0 / 56;

    const uint32_t Bsm = ab;
    const uint32_t Asm = ab + BRES_PAD;

    // ---- B resident fill
    for (int t = tid; t < BROWS * 16; t += 512) {
        int lp = t >> 4, u = t & 15;
        int gpp = r0 * 58 + lp;
        bool v = gpp < PPIX;
        uint32_t dst = Bsm + lp * 256 + ((u & 8) << 4) + ((((u & 7) ^ (lp & 7))) << 4);
        const char* src = (const char*)(g_xh + ((size_t)b * PPIX + (v ? gpp : 0)) * CIN + u * 8);
        cp16(dst, src, v ? 16 : 0);
    }

    // ---- A chunk loader (double-buffered, 16KB per chunk)
    auto load_A = [&](int ch) {
        int k = ch >> 1, cic = ch & 1;
        uint32_t buf = Asm + (uint32_t)(ch & 1) * ATILE_B;
        size_t aslab = (((size_t)b * 9 + k) * 2 + cic) * ((size_t)COUT * 64)
                     + (size_t)cotile * 128 * 64;
        const uint4* pAh = (const uint4*)(g_wh + aslab);
        #pragma unroll
        for (int j = 0; j < 2; j++) {
            int idx = tid + j * 512;
            uint32_t so = SW128(idx * 16);
            cp16(buf + so, pAh + idx, 16);
        }
    };

    // ---- ldmatrix address components
    const int aRow = wm * 32 + (lane & 15);
    const int aKb  = (lane >> 4) * 16;
    const int jlo  = (lane >> 3) & 1;
    const int rowin = ((lane >> 4) << 3) + (lane & 7);
    int lrB[2];
    #pragma unroll
    for (int nf = 0; nf < 2; nf++) {
        int n = wn * 32 + nf * 16 + rowin;
        int p = p0 + n;
        if (p >= HW) p = HW - 1;           // clamp; discarded in epilogue
        int r = p / 56, c = p - r * 56;
        lrB[nf] = (r - r0) * 58 + c;
    }

    float acc[2][4][4];
    #pragma unroll
    for (int mf = 0; mf < 2; mf++)
        #pragma unroll
        for (int j = 0; j < 4; j++)
            #pragma unroll
            for (int u = 0; u < 4; u++) acc[mf][j][u] = 0.f;

    load_A(0);
    CP_COMMIT();

    for (int ch = 0; ch < 18; ch++) {
        if (ch + 1 < 18) {
            load_A(ch + 1);
            CP_COMMIT();
            CP_WAIT(1);
        } else {
            CP_WAIT(0);
        }
        __syncthreads();

        const int k = ch >> 1, cic = ch & 1;
        const int kh = k / 3, kw = k - kh * 3;
        const int toff = kh * 58 + kw;
        const uint32_t ahB = Asm + (uint32_t)(ch & 1) * ATILE_B;
        const uint32_t cicOff = Bsm + cic * 128;

        #pragma unroll
        for (int s = 0; s < 4; s++) {
            const int ks = s * 32;
            uint32_t ah[2][4];
            #pragma unroll
            for (int mf = 0; mf < 2; mf++) {
                uint32_t off = SW128((aRow + mf * 16) * 128 + ks + aKb);
                LDSM4(ah[mf], ahB + off);
            }
            uint32_t bh[2][4];
            #pragma unroll
            for (int nf = 0; nf < 2; nf++) {
                int lr = lrB[nf] + toff;
                uint32_t addr = cicOff + lr * 256 + ((((s << 1) | jlo) ^ (lr & 7)) << 4);
                LDSM4(bh[nf], addr);
            }
            #pragma unroll
            for (int mf = 0; mf < 2; mf++)
                #pragma unroll
                for (int nf = 0; nf < 2; nf++) {
                    mma16816(acc[mf][nf * 2],     ah[mf], bh[nf][0], bh[nf][1]);
                    mma16816(acc[mf][nf * 2 + 1], ah[mf], bh[nf][2], bh[nf][3]);
                }
        }
        __syncthreads();
    }

    // ---- epilogue: stage through smem (128 x 132 f32), coalesced stores
    float* sout = (float*)mem;
    const int grp = lane >> 2, tg = lane & 3;
    #pragma unroll
    for (int mf = 0; mf < 2; mf++)
        #pragma unroll
        for (int j = 0; j < 4; j++) {
            int co_l = wm * 32 + mf * 16 + grp;
            int px_l = wn * 32 + j * 8 + tg * 2;
            sout[co_l * 132 + px_l]           = acc[mf][j][0];
            sout[co_l * 132 + px_l + 1]       = acc[mf][j][1];
            sout[(co_l + 8) * 132 + px_l]     = acc[mf][j][2];
            sout[(co_l + 8) * 132 + px_l + 1] = acc[mf][j][3];
        }
    __syncthreads();

    #pragma unroll
    for (int j = 0; j < 8; j++) {
        int idx = tid + j * 512;
        int row = idx >> 5, u = idx & 31;
        int px = u * 4;
        if (p0 + px + 3 < HW) {
            float4 v = *(float4*)(sout + row * 132 + px);
            float* dst = out + ((size_t)(b * COUT + cotile * 128 + row)) * HW + p0 + px;
            *(float4*)dst = v;
        }
    }
}

// ---------------------------------------------------------------------------
extern "C" void kernel_launch(void* const* d_in, const int* in_sizes, int n_in,
                              void* d_out, int out_size) {
    const float* x     = (const float*)d_in[0];
    const float* convs = (const float*)d_in[1];
    const float* w1    = (const float*)d_in[2];
    const float* b1    = (const float*)d_in[3];
    const float* w2    = (const float*)d_in[4];
    const float* b2    = (const float*)d_in[5];
    float* out = (float*)d_out;
    (void)in_sizes; (void)n_in; (void)out_size;

    cudaFuncSetAttribute(gemm_kernel,
                         cudaFuncAttributeMaxDynamicSharedMemorySize, SMEM_DYN);

    xborder_kernel<<<B_, 256>>>();                  // zeros borders + g_gap
    xsplit_kernel<<<dim3(98, B_), 256>>>(x);        // fills X + GAP partials
    router_kernel<<<B_, 32>>>(w1, b1, w2, b2);
    wmix_kernel<<<COUT, 288>>>(convs);
    gemm_kernel<<<dim3(NTILES, 2, B_), 512, SMEM_DYN>>>(out);
}

// round 10
// speedup vs baseline: 5.9003x; 1.0437x over previous
#include <cuda_runtime.h>
#include <cuda_fp16.h>
#include <cstdint>

// ---------------- problem constants ----------------
#define B_    32
#define CIN   128
#define COUT  256
#define HW    3136
#define HDIM  56
#define PD    58
#define PPIX  (PD*PD)     // 3364
#define EXP_  4
#define RDIM  16
#define NT    256
#define NTILES 13          // ceil(3136/256)

// ---------------- device scratch ----------------
__device__ float g_routing[B_ * EXP_];
__device__ float g_gap[B_ * CIN];     // raw channel sums (scaled in router)
// W fp16, GEMM layout: [b][k(9)][cic(2)][co(256)][cii(64)]
__device__ __align__(16) __half g_wh[(size_t)B_ * 9 * 2 * COUT * 64];
// X fp16, padded channel-last: [b][pp(3364)][ci(128)]
__device__ __align__(16) __half g_xh[(size_t)B_ * PPIX * CIN];

// ---------------- helpers ----------------
__device__ __forceinline__ uint32_t smem_u32(const void* p) {
    uint32_t a;
    asm("{ .reg .u64 t; cvta.to.shared.u64 t, %1; cvt.u32.u64 %0, t; }" : "=r"(a) : "l"(p));
    return a;
}
#define SW128(o) ((uint32_t)(o) ^ ((((uint32_t)(o)) >> 3) & 0x70))

__device__ __forceinline__ void cp16(uint32_t dst, const void* src, int sz) {
    asm volatile("cp.async.cg.shared.global [%0], [%1], 16, %2;"
                 :: "r"(dst), "l"(src), "r"(sz) : "memory");
}
#define CP_COMMIT() asm volatile("cp.async.commit_group;" ::: "memory")
#define CP_WAIT(n)  asm volatile("cp.async.wait_group %0;" :: "n"(n) : "memory")

#define LDSM4(r, a)                                                              \
    asm volatile("ldmatrix.sync.aligned.m8n8.x4.shared.b16 {%0,%1,%2,%3}, [%4];" \
        : "=r"((r)[0]), "=r"((r)[1]), "=r"((r)[2]), "=r"((r)[3]) : "r"(a))

__device__ __forceinline__ void mma16816(float* c, const uint32_t* a,
                                         uint32_t b0, uint32_t b1) {
    asm volatile(
        "mma.sync.aligned.m16n8k16.row.col.f32.f16.f16.f32 "
        "{%0,%1,%2,%3}, {%4,%5,%6,%7}, {%8,%9}, {%0,%1,%2,%3};"
        : "+f"(c[0]), "+f"(c[1]), "+f"(c[2]), "+f"(c[3])
        : "r"(a[0]), "r"(a[1]), "r"(a[2]), "r"(a[3]), "r"(b0), "r"(b1));
}

// ---------------------------------------------------------------------------
// Kernel A (runs FIRST): zero border pixels of padded X and zero g_gap.
// ---------------------------------------------------------------------------
__global__ void xborder_kernel() {
    int b = blockIdx.x;
    if (threadIdx.x < CIN) g_gap[b * CIN + threadIdx.x] = 0.f;
    uint4 z = {0, 0, 0, 0};
    for (int idx = threadIdx.x; idx < 228 * 16; idx += 256) {
        int i = idx >> 4, u = idx & 15;
        int pp;
        if (i < 58)       pp = i;
        else if (i < 116) pp = 57 * PD + (i - 58);
        else { int j = i - 116; pp = (1 + (j >> 1)) * PD + (j & 1) * 57; }
        size_t base = ((size_t)(b * PPIX + pp)) * CIN;
        ((uint4*)(g_xh + base))[u] = z;
    }
}

// ---------------------------------------------------------------------------
// Kernel B: transpose x -> padded channel-last fp16 + fused GAP accumulation.
// grid (98, 32), 256 threads.
// ---------------------------------------------------------------------------
__global__ void xsplit_kernel(const float* __restrict__ x) {
    __shared__ float s[CIN][33];
    int p0 = blockIdx.x * 32, b = blockIdx.y;
    int tid = threadIdx.x, lane = tid & 31, grp8 = tid >> 5;
    #pragma unroll 4
    for (int pass = 0; pass < 16; pass++) {
        int ci = pass * 8 + grp8;
        s[ci][lane] = x[((size_t)(b * CIN + ci)) * HW + p0 + lane];
    }
    __syncthreads();

    if (tid < CIN) {
        float sum = 0.f;
        #pragma unroll 8
        for (int j = 0; j < 32; j++) sum += s[tid][j];
        atomicAdd(&g_gap[b * CIN + tid], sum);
    }

    int pl = tid >> 3, g = tid & 7;
    int p = p0 + pl;
    int r = p / 56, c = p - r * 56;
    int pp = (r + 1) * PD + (c + 1);
    size_t base = ((size_t)(b * PPIX + pp)) * CIN + g * 16;
    __half hv[16];
    #pragma unroll
    for (int u = 0; u < 16; u++) hv[u] = __float2half_rn(s[g * 16 + u][pl]);
    *(uint4*)(g_xh + base)     = *(uint4*)(hv);
    *(uint4*)(g_xh + base + 8) = *(uint4*)(hv + 8);
}

// ---------------------------------------------------------------------------
// Kernel C: router MLP + softmax.  grid 32, 32 threads.
// ---------------------------------------------------------------------------
__global__ void router_kernel(const float* __restrict__ w1, const float* __restrict__ b1,
                              const float* __restrict__ w2, const float* __restrict__ b2) {
    int b = blockIdx.x, t = threadIdx.x;
    __shared__ float h[RDIM], lg[EXP_];
    const float invHW = 1.0f / (float)HW;
    if (t < RDIM) {
        float a = b1[t];
        const float* wr = w1 + t * CIN;
        const float* gp = g_gap + b * CIN;
        #pragma unroll 8
        for (int c = 0; c < CIN; c++) a = fmaf(wr[c], gp[c] * invHW, a);
        h[t] = fmaxf(a, 0.f);
    }
    __syncwarp();
    if (t < EXP_) {
        float a = b2[t];
        #pragma unroll
        for (int r = 0; r < RDIM; r++) a = fmaf(w2[t * RDIM + r], h[r], a);
        lg[t] = a;
    }
    __syncwarp();
    if (t == 0) {
        float m = fmaxf(fmaxf(lg[0], lg[1]), fmaxf(lg[2], lg[3]));
        float e[EXP_], ss = 0.f;
        #pragma unroll
        for (int i = 0; i < EXP_; i++) { e[i] = expf((lg[i] - m) * (1.0f / 30.0f)); ss += e[i]; }
        float inv = 1.0f / ss;
        #pragma unroll
        for (int i = 0; i < EXP_; i++) g_routing[b * EXP_ + i] = e[i] * inv;
    }
}

// ---------------------------------------------------------------------------
// Kernel D: mix experts -> fp16 W.  grid (256 co, 4 bgroups), 288 threads.
// Each block handles 8 samples; vectorized 8B stores.
// ---------------------------------------------------------------------------
__global__ void wmix_kernel(const float* __restrict__ convs) {
    int co = blockIdx.x, bg = blockIdx.y;
    int tid = threadIdx.x;
    __shared__ float se[EXP_][CIN * 9];
    for (int e = 0; e < EXP_; e++) {
        const float* src = convs + ((size_t)(e * COUT + co)) * (CIN * 9);
        for (int i = tid; i < CIN * 9; i += 288) se[e][i] = src[i];
    }
    __syncthreads();

    const int base = tid * 4;            // 288*4 = 1152
    const int k    = base / 128;
    const int rem  = base & 127;
    const int cic  = rem >> 6;
    const int cii  = rem & 63;

    for (int b = bg * 8; b < bg * 8 + 8; b++) {
        float r0 = g_routing[b * EXP_ + 0], r1 = g_routing[b * EXP_ + 1];
        float r2 = g_routing[b * EXP_ + 2], r3 = g_routing[b * EXP_ + 3];
        __half hv[4];
        #pragma unroll
        for (int u = 0; u < 4; u++) {
            int ci = cic * 64 + cii + u;
            int j = ci * 9 + k;
            float v = fmaf(r0, se[0][j], fmaf(r1, se[1][j], fmaf(r2, se[2][j], r3 * se[3][j])));
            hv[u] = __float2half_rn(v);
        }
        size_t d = ((((size_t)b * 9 + k) * 2 + cic) * COUT + co) * 64 + cii;
        *(uint2*)(g_wh + d) = *(uint2*)hv;
    }
}

// ---------------------------------------------------------------------------
// Kernel E: single-term fp16 implicit-GEMM conv, tap-resident B.
// grid (13, 2, 32), 512 threads (16 warps, 4x4), CTA tile 128co x 256px.
// Warp tile 32co x 64px.  B: 464 px-rows x 256B resident (116KB), loaded once.
// A: 16KB/chunk (9 taps x 2 ci halves) cp.async double-buffered.
// ---------------------------------------------------------------------------
#define BROWS    464
#define BRES_PAD (BROWS * 256)      // 118784
#define ATILE_B  16384
#define SMEM_DYN (BRES_PAD + 2 * ATILE_B + 1024)   // 152576

__global__ __launch_bounds__(512, 1)
void gemm_kernel(float* __restrict__ out) {
    extern __shared__ char dyn[];
    uint32_t sb = smem_u32(dyn);
    uint32_t ab = (sb + 1023u) & ~1023u;
    char* mem = dyn + (ab - sb);

    const int tid = threadIdx.x, w = tid >> 5, lane = tid & 31;
    const int wm = w & 3, wn = w >> 2;           // 4 x 4 warp grid
    const int ntile = blockIdx.x, cotile = blockIdx.y, b = blockIdx.z;
    const int p0 = ntile * NT;
    const int r0 = p0 / 56;

    const uint32_t Bsm = ab;
    const uint32_t Asm = ab + BRES_PAD;

    // ---- B resident fill: 464 px-rows x 256B, xor-swizzled 16B units
    for (int t = tid; t < BROWS * 16; t += 512) {
        int lp = t >> 4, u = t & 15;
        int gpp = r0 * 58 + lp;
        bool v = gpp < PPIX;
        uint32_t dst = Bsm + lp * 256 + ((u & 8) << 4) + ((((u & 7) ^ (lp & 7))) << 4);
        const char* src = (const char*)(g_xh + ((size_t)b * PPIX + (v ? gpp : 0)) * CIN + u * 8);
        cp16(dst, src, v ? 16 : 0);
    }

    // ---- A chunk loader (double-buffered, 16KB per chunk)
    auto load_A = [&](int ch) {
        int k = ch >> 1, cic = ch & 1;
        uint32_t buf = Asm + (uint32_t)(ch & 1) * ATILE_B;
        size_t aslab = (((size_t)b * 9 + k) * 2 + cic) * ((size_t)COUT * 64)
                     + (size_t)cotile * 128 * 64;
        const uint4* pAh = (const uint4*)(g_wh + aslab);
        #pragma unroll
        for (int j = 0; j < 2; j++) {
            int idx = tid + j * 512;
            uint32_t so = SW128(idx * 16);
            cp16(buf + so, pAh + idx, 16);
        }
    };

    // ---- ldmatrix address components
    const int aRow = wm * 32 + (lane & 15);
    const int aKb  = (lane >> 4) * 16;
    const int jlo  = (lane >> 3) & 1;
    const int rowin = ((lane >> 4) << 3) + (lane & 7);
    int lrB[4];
    #pragma unroll
    for (int nf = 0; nf < 4; nf++) {
        int n = wn * 64 + nf * 16 + rowin;
        int p = p0 + n;
        if (p >= HW) p = HW - 1;           // clamp; discarded in epilogue
        int r = p / 56, c = p - r * 56;
        lrB[nf] = (r - r0) * 58 + c;
    }

    float acc[2][8][4];
    #pragma unroll
    for (int mf = 0; mf < 2; mf++)
        #pragma unroll
        for (int j = 0; j < 8; j++)
            #pragma unroll
            for (int u = 0; u < 4; u++) acc[mf][j][u] = 0.f;

    load_A(0);
    CP_COMMIT();

    for (int ch = 0; ch < 18; ch++) {
        if (ch + 1 < 18) {
            load_A(ch + 1);
            CP_COMMIT();
            CP_WAIT(1);
        } else {
            CP_WAIT(0);
        }
        __syncthreads();

        const int k = ch >> 1, cic = ch & 1;
        const int kh = k / 3, kw = k - kh * 3;
        const int toff = kh * 58 + kw;
        const uint32_t ahB = Asm + (uint32_t)(ch & 1) * ATILE_B;
        const uint32_t cicOff = Bsm + cic * 128;

        #pragma unroll
        for (int s = 0; s < 4; s++) {
            const int ks = s * 32;
            uint32_t ah[2][4];
            #pragma unroll
            for (int mf = 0; mf < 2; mf++) {
                uint32_t off = SW128((aRow + mf * 16) * 128 + ks + aKb);
                LDSM4(ah[mf], ahB + off);
            }
            uint32_t bh[4][4];
            #pragma unroll
            for (int nf = 0; nf < 4; nf++) {
                int lr = lrB[nf] + toff;
                uint32_t addr = cicOff + lr * 256 + ((((s << 1) | jlo) ^ (lr & 7)) << 4);
                LDSM4(bh[nf], addr);
            }
            #pragma unroll
            for (int mf = 0; mf < 2; mf++)
                #pragma unroll
                for (int nf = 0; nf < 4; nf++) {
                    mma16816(acc[mf][nf * 2],     ah[mf], bh[nf][0], bh[nf][1]);
                    mma16816(acc[mf][nf * 2 + 1], ah[mf], bh[nf][2], bh[nf][3]);
                }
        }
        __syncthreads();
    }

    // ---- epilogue: stage through smem (128 x 260 f32), coalesced stores
    float* sout = (float*)mem;
    const int grp = lane >> 2, tg = lane & 3;
    #pragma unroll
    for (int mf = 0; mf < 2; mf++)
        #pragma unroll
        for (int j = 0; j < 8; j++) {
            int co_l = wm * 32 + mf * 16 + grp;
            int px_l = wn * 64 + j * 8 + tg * 2;
            sout[co_l * 260 + px_l]           = acc[mf][j][0];
            sout[co_l * 260 + px_l + 1]       = acc[mf][j][1];
            sout[(co_l + 8) * 260 + px_l]     = acc[mf][j][2];
            sout[(co_l + 8) * 260 + px_l + 1] = acc[mf][j][3];
        }
    __syncthreads();

    #pragma unroll
    for (int j = 0; j < 16; j++) {
        int idx = tid + j * 512;          // 8192 float4 units
        int row = idx >> 6, u = idx & 63;
        int px = u * 4;
        if (p0 + px + 3 < HW) {
            float4 v = *(float4*)(sout + row * 260 + px);
            float* dst = out + ((size_t)(b * COUT + cotile * 128 + row)) * HW + p0 + px;
            *(float4*)dst = v;
        }
    }
}

// ---------------------------------------------------------------------------
extern "C" void kernel_launch(void* const* d_in, const int* in_sizes, int n_in,
                              void* d_out, int out_size) {
    const float* x     = (const float*)d_in[0];
    const float* convs = (const float*)d_in[1];
    const float* w1    = (const float*)d_in[2];
    const float* b1    = (const float*)d_in[3];
    const float* w2    = (const float*)d_in[4];
    const float* b2    = (const float*)d_in[5];
    float* out = (float*)d_out;
    (void)in_sizes; (void)n_in; (void)out_size;

    cudaFuncSetAttribute(gemm_kernel,
                         cudaFuncAttributeMaxDynamicSharedMemorySize, SMEM_DYN);

    xborder_kernel<<<B_, 256>>>();
    xsplit_kernel<<<dim3(98, B_), 256>>>(x);
    router_kernel<<<B_, 32>>>(w1, b1, w2, b2);
    wmix_kernel<<<dim3(COUT, 4), 288>>>(convs);
    gemm_kernel<<<dim3(NTILES, 2, B_), 512, SMEM_DYN>>>(out);
}

// round 12
// speedup vs baseline: 5.9019x; 1.0003x over previous
#include <cuda_runtime.h>
#include <cuda_fp16.h>
#include <cstdint>

// ---------------- problem constants ----------------
#define B_    32
#define CIN   128
#define COUT  256
#define HW    3136
#define HDIM  56
#define PD    58
#define PPIX  (PD*PD)     // 3364
#define EXP_  4
#define RDIM  16
#define NT    256
#define NTILES 13          // ceil(3136/256)

// ---------------- device scratch ----------------
__device__ float g_routing[B_ * EXP_];
__device__ float g_gap[B_ * CIN];     // raw channel sums (scaled in router)
// W fp16, GEMM layout: [b][k(9)][cic(2)][co(256)][cii(64)]
__device__ __align__(16) __half g_wh[(size_t)B_ * 9 * 2 * COUT * 64];
// X fp16, padded channel-last: [b][pp(3364)][ci(128)]
__device__ __align__(16) __half g_xh[(size_t)B_ * PPIX * CIN];

// ---------------- helpers ----------------
__device__ __forceinline__ uint32_t smem_u32(const void* p) {
    uint32_t a;
    asm("{ .reg .u64 t; cvta.to.shared.u64 t, %1; cvt.u32.u64 %0, t; }" : "=r"(a) : "l"(p));
    return a;
}
#define SW128(o) ((uint32_t)(o) ^ ((((uint32_t)(o)) >> 3) & 0x70))

__device__ __forceinline__ void cp16(uint32_t dst, const void* src, int sz) {
    asm volatile("cp.async.cg.shared.global [%0], [%1], 16, %2;"
                 :: "r"(dst), "l"(src), "r"(sz) : "memory");
}
#define CP_COMMIT() asm volatile("cp.async.commit_group;" ::: "memory")
#define CP_WAIT(n)  asm volatile("cp.async.wait_group %0;" :: "n"(n) : "memory")

#define LDSM4(r, a)                                                              \
    asm volatile("ldmatrix.sync.aligned.m8n8.x4.shared.b16 {%0,%1,%2,%3}, [%4];" \
        : "=r"((r)[0]), "=r"((r)[1]), "=r"((r)[2]), "=r"((r)[3]) : "r"(a))

__device__ __forceinline__ void mma16816(float* c, const uint32_t* a,
                                         uint32_t b0, uint32_t b1) {
    asm volatile(
        "mma.sync.aligned.m16n8k16.row.col.f32.f16.f16.f32 "
        "{%0,%1,%2,%3}, {%4,%5,%6,%7}, {%8,%9}, {%0,%1,%2,%3};"
        : "+f"(c[0]), "+f"(c[1]), "+f"(c[2]), "+f"(c[3])
        : "r"(a[0]), "r"(a[1]), "r"(a[2]), "r"(a[3]), "r"(b0), "r"(b1));
}

// ---------------------------------------------------------------------------
// Kernel A (runs FIRST): zero border pixels of padded X and zero g_gap.
// ---------------------------------------------------------------------------
__global__ void xborder_kernel() {
    int b = blockIdx.x;
    if (threadIdx.x < CIN) g_gap[b * CIN + threadIdx.x] = 0.f;
    uint4 z = {0, 0, 0, 0};
    for (int idx = threadIdx.x; idx < 228 * 16; idx += 256) {
        int i = idx >> 4, u = idx & 15;
        int pp;
        if (i < 58)       pp = i;
        else if (i < 116) pp = 57 * PD + (i - 58);
        else { int j = i - 116; pp = (1 + (j >> 1)) * PD + (j & 1) * 57; }
        size_t base = ((size_t)(b * PPIX + pp)) * CIN;
        ((uint4*)(g_xh + base))[u] = z;
    }
}

// ---------------------------------------------------------------------------
// Kernel B: transpose x -> padded channel-last fp16 + fused GAP accumulation.
// grid (98, 32), 256 threads.
// ---------------------------------------------------------------------------
__global__ void xsplit_kernel(const float* __restrict__ x) {
    __shared__ float s[CIN][33];
    int p0 = blockIdx.x * 32, b = blockIdx.y;
    int tid = threadIdx.x, lane = tid & 31, grp8 = tid >> 5;
    #pragma unroll 4
    for (int pass = 0; pass < 16; pass++) {
        int ci = pass * 8 + grp8;
        s[ci][lane] = x[((size_t)(b * CIN + ci)) * HW + p0 + lane];
    }
    __syncthreads();

    if (tid < CIN) {
        float sum = 0.f;
        #pragma unroll 8
        for (int j = 0; j < 32; j++) sum += s[tid][j];
        atomicAdd(&g_gap[b * CIN + tid], sum);
    }

    int pl = tid >> 3, g = tid & 7;
    int p = p0 + pl;
    int r = p / 56, c = p - r * 56;
    int pp = (r + 1) * PD + (c + 1);
    size_t base = ((size_t)(b * PPIX + pp)) * CIN + g * 16;
    __half hv[16];
    #pragma unroll
    for (int u = 0; u < 16; u++) hv[u] = __float2half_rn(s[g * 16 + u][pl]);
    *(uint4*)(g_xh + base)     = *(uint4*)(hv);
    *(uint4*)(g_xh + base + 8) = *(uint4*)(hv + 8);
}

// ---------------------------------------------------------------------------
// Kernel C: router MLP + softmax.  grid 32, 32 threads.
// ---------------------------------------------------------------------------
__global__ void router_kernel(const float* __restrict__ w1, const float* __restrict__ b1,
                              const float* __restrict__ w2, const float* __restrict__ b2) {
    int b = blockIdx.x, t = threadIdx.x;
    __shared__ float h[RDIM], lg[EXP_];
    const float invHW = 1.0f / (float)HW;
    if (t < RDIM) {
        float a = b1[t];
        const float* wr = w1 + t * CIN;
        const float* gp = g_gap + b * CIN;
        #pragma unroll 8
        for (int c = 0; c < CIN; c++) a = fmaf(wr[c], gp[c] * invHW, a);
        h[t] = fmaxf(a, 0.f);
    }
    __syncwarp();
    if (t < EXP_) {
        float a = b2[t];
        #pragma unroll
        for (int r = 0; r < RDIM; r++) a = fmaf(w2[t * RDIM + r], h[r], a);
        lg[t] = a;
    }
    __syncwarp();
    if (t == 0) {
        float m = fmaxf(fmaxf(lg[0], lg[1]), fmaxf(lg[2], lg[3]));
        float e[EXP_], ss = 0.f;
        #pragma unroll
        for (int i = 0; i < EXP_; i++) { e[i] = expf((lg[i] - m) * (1.0f / 30.0f)); ss += e[i]; }
        float inv = 1.0f / ss;
        #pragma unroll
        for (int i = 0; i < EXP_; i++) g_routing[b * EXP_ + i] = e[i] * inv;
    }
}

// ---------------------------------------------------------------------------
// Kernel D: mix experts -> fp16 W.  grid (256 co, 8 bgroups), 288 threads.
// Each block handles 4 samples; vectorized 8B stores.
// ---------------------------------------------------------------------------
__global__ void wmix_kernel(const float* __restrict__ convs) {
    int co = blockIdx.x, bg = blockIdx.y;
    int tid = threadIdx.x;
    __shared__ float se[EXP_][CIN * 9];
    for (int e = 0; e < EXP_; e++) {
        const float* src = convs + ((size_t)(e * COUT + co)) * (CIN * 9);
        for (int i = tid; i < CIN * 9; i += 288) se[e][i] = src[i];
    }
    __syncthreads();

    const int base = tid * 4;            // 288*4 = 1152
    const int k    = base / 128;
    const int rem  = base & 127;
    const int cic  = rem >> 6;
    const int cii  = rem & 63;

    for (int b = bg * 4; b < bg * 4 + 4; b++) {
        float r0 = g_routing[b * EXP_ + 0], r1 = g_routing[b * EXP_ + 1];
        float r2 = g_routing[b * EXP_ + 2], r3 = g_routing[b * EXP_ + 3];
        __half hv[4];
        #pragma unroll
        for (int u = 0; u < 4; u++) {
            int ci = cic * 64 + cii + u;
            int j = ci * 9 + k;
            float v = fmaf(r0, se[0][j], fmaf(r1, se[1][j], fmaf(r2, se[2][j], r3 * se[3][j])));
            hv[u] = __float2half_rn(v);
        }
        size_t d = ((((size_t)b * 9 + k) * 2 + cic) * COUT + co) * 64 + cii;
        *(uint2*)(g_wh + d) = *(uint2*)hv;
    }
}

// ---------------------------------------------------------------------------
// Kernel E: single-term fp16 implicit-GEMM conv, tap-resident B, 3-stage A.
// grid (13, 2, 32), 512 threads (16 warps, 4x4), CTA tile 128co x 256px.
// B: 464 px-rows x 256B resident (116KB), loaded once.
// A: 16KB/chunk, 3 buffers, ONE __syncthreads per chunk.
// ---------------------------------------------------------------------------
#define BROWS    464
#define BRES_PAD (BROWS * 256)      // 118784
#define ATILE_B  16384
#define SMEM_DYN (BRES_PAD + 3 * ATILE_B + 1024)   // 168960

__global__ __launch_bounds__(512, 1)
void gemm_kernel(float* __restrict__ out) {
    extern __shared__ char dyn[];
    uint32_t sb = smem_u32(dyn);
    uint32_t ab = (sb + 1023u) & ~1023u;
    char* mem = dyn + (ab - sb);

    const int tid = threadIdx.x, w = tid >> 5, lane = tid & 31;
    const int wm = w & 3, wn = w >> 2;           // 4 x 4 warp grid
    const int ntile = blockIdx.x, cotile = blockIdx.y, b = blockIdx.z;
    const int p0 = ntile * NT;
    const int r0 = p0 / 56;

    const uint32_t Bsm = ab;
    const uint32_t Asm = ab + BRES_PAD;

    // ---- B resident fill (lands in cp.async group 0)
    for (int t = tid; t < BROWS * 16; t += 512) {
        int lp = t >> 4, u = t & 15;
        int gpp = r0 * 58 + lp;
        bool v = gpp < PPIX;
        uint32_t dst = Bsm + lp * 256 + ((u & 8) << 4) + ((((u & 7) ^ (lp & 7))) << 4);
        const char* src = (const char*)(g_xh + ((size_t)b * PPIX + (v ? gpp : 0)) * CIN + u * 8);
        cp16(dst, src, v ? 16 : 0);
    }

    // ---- A chunk loader (triple-buffered, 16KB per chunk)
    auto load_A = [&](int ch) {
        int k = ch >> 1, cic = ch & 1;
        uint32_t buf = Asm + (uint32_t)(ch % 3) * ATILE_B;
        size_t aslab = (((size_t)b * 9 + k) * 2 + cic) * ((size_t)COUT * 64)
                     + (size_t)cotile * 128 * 64;
        const uint4* pAh = (const uint4*)(g_wh + aslab);
        #pragma unroll
        for (int j = 0; j < 2; j++) {
            int idx = tid + j * 512;
            uint32_t so = SW128(idx * 16);
            cp16(buf + so, pAh + idx, 16);
        }
    };

    // ---- ldmatrix address components
    const int aRow = wm * 32 + (lane & 15);
    const int aKb  = (lane >> 4) * 16;
    const int jlo  = (lane >> 3) & 1;
    const int rowin = ((lane >> 4) << 3) + (lane & 7);
    int lrB[4];
    #pragma unroll
    for (int nf = 0; nf < 4; nf++) {
        int n = wn * 64 + nf * 16 + rowin;
        int p = p0 + n;
        if (p >= HW) p = HW - 1;           // clamp; discarded in epilogue
        int r = p / 56, c = p - r * 56;
        lrB[nf] = (r - r0) * 58 + c;
    }

    float acc[2][8][4];
    #pragma unroll
    for (int mf = 0; mf < 2; mf++)
        #pragma unroll
        for (int j = 0; j < 8; j++)
            #pragma unroll
            for (int u = 0; u < 4; u++) acc[mf][j][u] = 0.f;

    load_A(0);
    CP_COMMIT();          // group 0: B fill + A0
    load_A(1);
    CP_COMMIT();          // group 1: A1

    for (int ch = 0; ch < 18; ch++) {
        // wait until A[ch] (group ch) is complete
        if (ch == 17) { CP_WAIT(0); } else { CP_WAIT(1); }
        __syncthreads();   // also proves compute(ch-1) finished in all warps

        if (ch + 2 < 18) {
            load_A(ch + 2);          // overwrites buf[(ch-1)%3] -- safe
            CP_COMMIT();
        }

        const int k = ch >> 1, cic = ch & 1;
        const int kh = k / 3, kw = k - kh * 3;
        const int toff = kh * 58 + kw;
        const uint32_t ahB = Asm + (uint32_t)(ch % 3) * ATILE_B;
        const uint32_t cicOff = Bsm + cic * 128;

        #pragma unroll
        for (int s = 0; s < 4; s++) {
            const int ks = s * 32;
            uint32_t ah[2][4];
            #pragma unroll
            for (int mf = 0; mf < 2; mf++) {
                uint32_t off = SW128((aRow + mf * 16) * 128 + ks + aKb);
                LDSM4(ah[mf], ahB + off);
            }
            uint32_t bh[4][4];
            #pragma unroll
            for (int nf = 0; nf < 4; nf++) {
                int lr = lrB[nf] + toff;
                uint32_t addr = cicOff + lr * 256 + ((((s << 1) | jlo) ^ (lr & 7)) << 4);
                LDSM4(bh[nf], addr);
            }
            #pragma unroll
            for (int mf = 0; mf < 2; mf++)
                #pragma unroll
                for (int nf = 0; nf < 4; nf++) {
                    mma16816(acc[mf][nf * 2],     ah[mf], bh[nf][0], bh[nf][1]);
                    mma16816(acc[mf][nf * 2 + 1], ah[mf], bh[nf][2], bh[nf][3]);
                }
        }
    }
    __syncthreads();   // all compute done before smem reuse

    // ---- epilogue: stage through smem (128 x 260 f32), coalesced stores
    float* sout = (float*)mem;
    const int grp = lane >> 2, tg = lane & 3;
    #pragma unroll
    for (int mf = 0; mf < 2; mf++)
        #pragma unroll
        for (int j = 0; j < 8; j++) {
            int co_l = wm * 32 + mf * 16 + grp;
            int px_l = wn * 64 + j * 8 + tg * 2;
            sout[co_l * 260 + px_l]           = acc[mf][j][0];
            sout[co_l * 260 + px_l + 1]       = acc[mf][j][1];
            sout[(co_l + 8) * 260 + px_l]     = acc[mf][j][2];
            sout[(co_l + 8) * 260 + px_l + 1] = acc[mf][j][3];
        }
    __syncthreads();

    #pragma unroll
    for (int j = 0; j < 16; j++) {
        int idx = tid + j * 512;          // 8192 float4 units
        int row = idx >> 6, u = idx & 63;
        int px = u * 4;
        if (p0 + px + 3 < HW) {
            float4 v = *(float4*)(sout + row * 260 + px);
            float* dst = out + ((size_t)(b * COUT + cotile * 128 + row)) * HW + p0 + px;
            *(float4*)dst = v;
        }
    }
}

// ---------------------------------------------------------------------------
extern "C" void kernel_launch(void* const* d_in, const int* in_sizes, int n_in,
                              void* d_out, int out_size) {
    const float* x     = (const float*)d_in[0];
    const float* convs = (const float*)d_in[1];
    const float* w1    = (const float*)d_in[2];
    const float* b1    = (const float*)d_in[3];
    const float* w2    = (const float*)d_in[4];
    const float* b2    = (const float*)d_in[5];
    float* out = (float*)d_out;
    (void)in_sizes; (void)n_in; (void)out_size;

    cudaFuncSetAttribute(gemm_kernel,
                         cudaFuncAttributeMaxDynamicSharedMemorySize, SMEM_DYN);

    xborder_kernel<<<B_, 256>>>();
    xsplit_kernel<<<dim3(98, B_), 256>>>(x);
    router_kernel<<<B_, 32>>>(w1, b1, w2, b2);
    wmix_kernel<<<dim3(COUT, 8), 288>>>(convs);
    gemm_kernel<<<dim3(NTILES, 2, B_), 512, SMEM_DYN>>>(out);
}

// round 13
// speedup vs baseline: 6.7500x; 1.1437x over previous
#include <cuda_runtime.h>
#include <cuda_fp16.h>
#include <cstdint>

// ---------------- problem constants ----------------
#define B_    32
#define CIN   128
#define COUT  256
#define HW    3136
#define HDIM  56
#define PD    58
#define PPIX  (PD*PD)     // 3364
#define EXP_  4
#define RDIM  16
#define TILES 784          // 28x28 Winograd F(2x2,3x3) tiles
#define TT    64           // tiles per gemm CTA
#define TTILES 13          // ceil(784/64)

// ---------------- device scratch ----------------
__device__ float g_routing[B_ * EXP_];
__device__ float g_gap[B_ * CIN];
// U = GgG^T fp16: [b][comp16][co256][ci128]
__device__ __align__(16) __half g_u[(size_t)B_ * 16 * COUT * CIN];
// V = B^TdB fp16: [b][comp16][tile784][ci128]
__device__ __align__(16) __half g_v[(size_t)B_ * 16 * TILES * CIN];
// X fp16, padded channel-last: [b][pp 3364][ci 128]
__device__ __align__(16) __half g_xh[(size_t)B_ * PPIX * CIN];

// ---------------- helpers ----------------
__device__ __forceinline__ uint32_t smem_u32(const void* p) {
    uint32_t a;
    asm("{ .reg .u64 t; cvta.to.shared.u64 t, %1; cvt.u32.u64 %0, t; }" : "=r"(a) : "l"(p));
    return a;
}
__device__ __forceinline__ void cp16(uint32_t dst, const void* src, int sz) {
    asm volatile("cp.async.cg.shared.global [%0], [%1], 16, %2;"
                 :: "r"(dst), "l"(src), "r"(sz) : "memory");
}
#define CP_COMMIT() asm volatile("cp.async.commit_group;" ::: "memory")
#define CP_WAIT(n)  asm volatile("cp.async.wait_group %0;" :: "n"(n) : "memory")

#define LDSM4(r, a)                                                              \
    asm volatile("ldmatrix.sync.aligned.m8n8.x4.shared.b16 {%0,%1,%2,%3}, [%4];" \
        : "=r"((r)[0]), "=r"((r)[1]), "=r"((r)[2]), "=r"((r)[3]) : "r"(a))

__device__ __forceinline__ void mma16816(float* c, const uint32_t* a,
                                         uint32_t b0, uint32_t b1) {
    asm volatile(
        "mma.sync.aligned.m16n8k16.row.col.f32.f16.f16.f32 "
        "{%0,%1,%2,%3}, {%4,%5,%6,%7}, {%8,%9}, {%0,%1,%2,%3};"
        : "+f"(c[0]), "+f"(c[1]), "+f"(c[2]), "+f"(c[3])
        : "r"(a[0]), "r"(a[1]), "r"(a[2]), "r"(a[3]), "r"(b0), "r"(b1));
}

// ---------------------------------------------------------------------------
// Kernel A: zero border pixels of padded X and zero g_gap.
// ---------------------------------------------------------------------------
__global__ void xborder_kernel() {
    int b = blockIdx.x;
    if (threadIdx.x < CIN) g_gap[b * CIN + threadIdx.x] = 0.f;
    uint4 z = {0, 0, 0, 0};
    for (int idx = threadIdx.x; idx < 228 * 16; idx += 256) {
        int i = idx >> 4, u = idx & 15;
        int pp;
        if (i < 58)       pp = i;
        else if (i < 116) pp = 57 * PD + (i - 58);
        else { int j = i - 116; pp = (1 + (j >> 1)) * PD + (j & 1) * 57; }
        size_t base = ((size_t)(b * PPIX + pp)) * CIN;
        ((uint4*)(g_xh + base))[u] = z;
    }
}

// ---------------------------------------------------------------------------
// Kernel B: transpose x -> padded channel-last fp16 + fused GAP partials.
// ---------------------------------------------------------------------------
__global__ void xsplit_kernel(const float* __restrict__ x) {
    __shared__ float s[CIN][33];
    int p0 = blockIdx.x * 32, b = blockIdx.y;
    int tid = threadIdx.x, lane = tid & 31, grp8 = tid >> 5;
    #pragma unroll 4
    for (int pass = 0; pass < 16; pass++) {
        int ci = pass * 8 + grp8;
        s[ci][lane] = x[((size_t)(b * CIN + ci)) * HW + p0 + lane];
    }
    __syncthreads();

    if (tid < CIN) {
        float sum = 0.f;
        #pragma unroll 8
        for (int j = 0; j < 32; j++) sum += s[tid][j];
        atomicAdd(&g_gap[b * CIN + tid], sum);
    }

    int pl = tid >> 3, g = tid & 7;
    int p = p0 + pl;
    int r = p / 56, c = p - r * 56;
    int pp = (r + 1) * PD + (c + 1);
    size_t base = ((size_t)(b * PPIX + pp)) * CIN + g * 16;
    __half hv[16];
    #pragma unroll
    for (int u = 0; u < 16; u++) hv[u] = __float2half_rn(s[g * 16 + u][pl]);
    *(uint4*)(g_xh + base)     = *(uint4*)(hv);
    *(uint4*)(g_xh + base + 8) = *(uint4*)(hv + 8);
}

// ---------------------------------------------------------------------------
// Kernel C: router MLP + softmax.  grid 32, 32 threads.
// ---------------------------------------------------------------------------
__global__ void router_kernel(const float* __restrict__ w1, const float* __restrict__ b1,
                              const float* __restrict__ w2, const float* __restrict__ b2) {
    int b = blockIdx.x, t = threadIdx.x;
    __shared__ float h[RDIM], lg[EXP_];
    const float invHW = 1.0f / (float)HW;
    if (t < RDIM) {
        float a = b1[t];
        const float* wr = w1 + t * CIN;
        const float* gp = g_gap + b * CIN;
        #pragma unroll 8
        for (int c = 0; c < CIN; c++) a = fmaf(wr[c], gp[c] * invHW, a);
        h[t] = fmaxf(a, 0.f);
    }
    __syncwarp();
    if (t < EXP_) {
        float a = b2[t];
        #pragma unroll
        for (int r = 0; r < RDIM; r++) a = fmaf(w2[t * RDIM + r], h[r], a);
        lg[t] = a;
    }
    __syncwarp();
    if (t == 0) {
        float m = fmaxf(fmaxf(lg[0], lg[1]), fmaxf(lg[2], lg[3]));
        float e[EXP_], ss = 0.f;
        #pragma unroll
        for (int i = 0; i < EXP_; i++) { e[i] = expf((lg[i] - m) * (1.0f / 30.0f)); ss += e[i]; }
        float inv = 1.0f / ss;
        #pragma unroll
        for (int i = 0; i < EXP_; i++) g_routing[b * EXP_ + i] = e[i] * inv;
    }
}

// ---------------------------------------------------------------------------
// Kernel D: mix experts + Winograd weight transform U = G g G^T -> fp16.
// grid (256 co, 4 bg), 128 threads (one ci each), 8 samples per block.
// ---------------------------------------------------------------------------
__global__ void umix_kernel(const float* __restrict__ convs) {
    int co = blockIdx.x, bg = blockIdx.y;
    int ci = threadIdx.x;
    __shared__ float se[EXP_][CIN * 9];
    for (int e = 0; e < EXP_; e++) {
        const float* src = convs + ((size_t)(e * COUT + co)) * (CIN * 9);
        for (int i = ci; i < CIN * 9; i += 128) se[e][i] = src[i];
    }
    __syncthreads();

    for (int b = bg * 8; b < bg * 8 + 8; b++) {
        float r0 = g_routing[b * EXP_ + 0], r1 = g_routing[b * EXP_ + 1];
        float r2 = g_routing[b * EXP_ + 2], r3 = g_routing[b * EXP_ + 3];
        float m[9];
        #pragma unroll
        for (int k = 0; k < 9; k++) {
            int j = ci * 9 + k;
            m[k] = fmaf(r0, se[0][j], fmaf(r1, se[1][j], fmaf(r2, se[2][j], r3 * se[3][j])));
        }
        // q = G g  (4x3)
        float q[4][3];
        #pragma unroll
        for (int c = 0; c < 3; c++) {
            q[0][c] = m[c];
            q[1][c] = 0.5f * (m[c] + m[3 + c] + m[6 + c]);
            q[2][c] = 0.5f * (m[c] - m[3 + c] + m[6 + c]);
            q[3][c] = m[6 + c];
        }
        // U = q G^T (4x4)
        #pragma unroll
        for (int u = 0; u < 4; u++) {
            float U0 = q[u][0];
            float U1 = 0.5f * (q[u][0] + q[u][1] + q[u][2]);
            float U2 = 0.5f * (q[u][0] - q[u][1] + q[u][2]);
            float U3 = q[u][2];
            size_t base = ((size_t)(b * 16 + u * 4) * COUT + co) * CIN + ci;
            size_t cstep = (size_t)COUT * CIN;
            g_u[base]             = __float2half_rn(U0);
            g_u[base + cstep]     = __float2half_rn(U1);
            g_u[base + 2 * cstep] = __float2half_rn(U2);
            g_u[base + 3 * cstep] = __float2half_rn(U3);
        }
    }
}

// ---------------------------------------------------------------------------
// Kernel E: Winograd input transform V = B^T d B  -> fp16.
// grid (28 tile-rows, 32 b), 256 threads.  Smem: 4 padded rows x 58 x 128 fp16.
// ---------------------------------------------------------------------------
#define VT_SMEM (4 * PD * CIN * 2)   // 59392
__global__ void vtrans_kernel() {
    extern __shared__ char vsm[];
    int tr = blockIdx.x, b = blockIdx.y;
    int tid = threadIdx.x;

    const uint4* src = (const uint4*)(g_xh + ((size_t)b * PPIX + 2 * tr * PD) * CIN);
    uint4* dst = (uint4*)vsm;
    for (int t = tid; t < VT_SMEM / 16; t += 256) dst[t] = src[t];
    __syncthreads();

    const __half* s16 = (const __half*)vsm;
    #pragma unroll
    for (int it = 0; it < 14; it++) {
        int item = it * 256 + tid;
        int ci = item & 127, tc = item >> 7;        // tc 0..27
        float d[4][4];
        #pragma unroll
        for (int r = 0; r < 4; r++)
            #pragma unroll
            for (int c = 0; c < 4; c++)
                d[r][c] = __half2float(s16[((size_t)(r * PD + 2 * tc + c)) * CIN + ci]);
        // e = B^T d
        float e[4][4];
        #pragma unroll
        for (int c = 0; c < 4; c++) {
            e[0][c] = d[0][c] - d[2][c];
            e[1][c] = d[1][c] + d[2][c];
            e[2][c] = d[2][c] - d[1][c];
            e[3][c] = d[1][c] - d[3][c];
        }
        int t = tr * 28 + tc;
        size_t base = ((size_t)(b * 16) * TILES + t) * CIN + ci;
        size_t cstep = (size_t)TILES * CIN;
        #pragma unroll
        for (int u = 0; u < 4; u++) {
            float V0 = e[u][0] - e[u][2];
            float V1 = e[u][1] + e[u][2];
            float V2 = e[u][2] - e[u][1];
            float V3 = e[u][1] - e[u][3];
            g_v[base + (u * 4 + 0) * cstep] = __float2half_rn(V0);
            g_v[base + (u * 4 + 1) * cstep] = __float2half_rn(V1);
            g_v[base + (u * 4 + 2) * cstep] = __float2half_rn(V2);
            g_v[base + (u * 4 + 3) * cstep] = __float2half_rn(V3);
        }
    }
}

// ---------------------------------------------------------------------------
// Kernel F: Winograd GEMM + output transform.
// grid (13 ttile, 2 cotile, 32 b), 512 threads (16 warps, 4 wm x 4 wn).
// Per comp (16): A = U[128co x 128ci] (32KB), B = V[64t x 128ci] (16KB),
// 3-stage cp.async pipeline.  M accumulated per comp in regs, folded into
// 2x2 output accumulators via A^T M A (coeffs 0/+-1, constant-folded).
// ---------------------------------------------------------------------------
#define STAGE_B 49152                      // 16KB B + 32KB A
#define SMEM_DYN (3 * STAGE_B + 1024)      // 148480

__global__ __launch_bounds__(512, 1)
void wgemm_kernel(float* __restrict__ out) {
    extern __shared__ char dyn[];
    uint32_t sb = smem_u32(dyn);
    uint32_t ab = (sb + 1023u) & ~1023u;

    const int tid = threadIdx.x, w = tid >> 5, lane = tid & 31;
    const int wm = w & 3, wn = w >> 2;
    const int ttile = blockIdx.x, cotile = blockIdx.y, b = blockIdx.z;
    const int t0 = ttile * TT;

    // loader: B (1024 x 16B) + A (2048 x 16B) into stage c%3
    auto load_comp = [&](int c) {
        uint32_t stg = ab + (uint32_t)(c % 3) * STAGE_B;
        const __half* vslab = g_v + ((size_t)(b * 16 + c)) * TILES * CIN;
        #pragma unroll
        for (int j = 0; j < 2; j++) {
            int idx = tid + j * 512;
            int row = idx >> 4, u = idx & 15;
            int t = t0 + row;
            bool v = t < TILES;
            uint32_t so = stg + row * 256 + ((u & 8) << 4) + (((u & 7) ^ (row & 7)) << 4);
            cp16(so, vslab + (size_t)(v ? t : 0) * CIN + u * 8, v ? 16 : 0);
        }
        const __half* uslab = g_u + ((size_t)(b * 16 + c) * COUT + cotile * 128) * CIN;
        uint32_t abase = stg + 16384;
        #pragma unroll
        for (int j = 0; j < 4; j++) {
            int idx = tid + j * 512;
            int row = idx >> 4, u = idx & 15;
            uint32_t so = abase + row * 256 + ((u & 8) << 4) + (((u & 7) ^ (row & 7)) << 4);
            cp16(so, uslab + (size_t)row * CIN + u * 8, 16);
        }
    };

    const int aR0  = wm * 32 + (lane & 15);
    const int aSel = lane >> 4;
    const int jlo  = (lane >> 3) & 1;
    const int rowin = ((lane >> 4) << 3) + (lane & 7);
    const int brow = wn * 16 + rowin;
    const int grp = lane >> 2, tg = lane & 3;

    static const float KA[2][4] = {{1.f, 1.f, 1.f, 0.f}, {0.f, 1.f, -1.f, -1.f}};

    float oacc[2][2][4][4];
    #pragma unroll
    for (int a0 = 0; a0 < 2; a0++)
        #pragma unroll
        for (int a1 = 0; a1 < 2; a1++)
            #pragma unroll
            for (int a2 = 0; a2 < 4; a2++)
                #pragma unroll
                for (int a3 = 0; a3 < 4; a3++) oacc[a0][a1][a2][a3] = 0.f;

    load_comp(0);
    CP_COMMIT();
    load_comp(1);
    CP_COMMIT();

    #pragma unroll
    for (int c = 0; c < 16; c++) {
        if (c == 15) { CP_WAIT(0); } else { CP_WAIT(1); }
        __syncthreads();
        if (c + 2 < 16) { load_comp(c + 2); CP_COMMIT(); }

        uint32_t stg = ab + (uint32_t)(c % 3) * STAGE_B;
        uint32_t Bb = stg, Ab = stg + 16384;

        float macc[2][2][4];
        #pragma unroll
        for (int mf = 0; mf < 2; mf++)
            #pragma unroll
            for (int nf = 0; nf < 2; nf++)
                #pragma unroll
                for (int u = 0; u < 4; u++) macc[mf][nf][u] = 0.f;

        #pragma unroll
        for (int s = 0; s < 8; s++) {
            uint32_t ah[2][4], bh[4];
            #pragma unroll
            for (int mf = 0; mf < 2; mf++) {
                int row = aR0 + mf * 16;
                int u = (s << 1) | aSel;
                uint32_t off = row * 256 + ((u & 8) << 4) + (((u & 7) ^ (row & 7)) << 4);
                LDSM4(ah[mf], Ab + off);
            }
            {
                int u = (s << 1) | jlo;
                uint32_t off = brow * 256 + ((u & 8) << 4) + (((u & 7) ^ (brow & 7)) << 4);
                LDSM4(bh, Bb + off);
            }
            #pragma unroll
            for (int mf = 0; mf < 2; mf++) {
                mma16816(macc[mf][0], ah[mf], bh[0], bh[1]);
                mma16816(macc[mf][1], ah[mf], bh[2], bh[3]);
            }
        }

        // fold M_comp into output accumulators: coeff = KA[i][u]*KA[j][v]
        const int cu = c >> 2, cv = c & 3;
        #pragma unroll
        for (int i = 0; i < 2; i++)
            #pragma unroll
            for (int j = 0; j < 2; j++) {
                float kc = KA[i][cu] * KA[j][cv];
                if (kc != 0.f) {
                    #pragma unroll
                    for (int mf = 0; mf < 2; mf++)
                        #pragma unroll
                        for (int nf = 0; nf < 2; nf++)
                            #pragma unroll
                            for (int r4 = 0; r4 < 4; r4++)
                                oacc[mf][nf][r4][i * 2 + j] =
                                    fmaf(kc, macc[mf][nf][r4], oacc[mf][nf][r4][i * 2 + j]);
                }
            }
    }

    // ---- epilogue: direct float4 stores (tile pairs are even -> aligned)
    #pragma unroll
    for (int mf = 0; mf < 2; mf++)
        #pragma unroll
        for (int nf = 0; nf < 2; nf++) {
            int t_a = t0 + wn * 16 + nf * 8 + 2 * tg;
            if (t_a < TILES) {
                int tr = t_a / 28, tc = t_a % 28;
                #pragma unroll
                for (int ch = 0; ch < 2; ch++) {
                    int co = cotile * 128 + wm * 32 + mf * 16 + grp + ch * 8;
                    float* base = out + ((size_t)(b * COUT + co)) * HW;
                    #pragma unroll
                    for (int i = 0; i < 2; i++) {
                        float4 v;
                        v.x = oacc[mf][nf][ch * 2 + 0][i * 2 + 0];
                        v.y = oacc[mf][nf][ch * 2 + 0][i * 2 + 1];
                        v.z = oacc[mf][nf][ch * 2 + 1][i * 2 + 0];
                        v.w = oacc[mf][nf][ch * 2 + 1][i * 2 + 1];
                        *(float4*)(base + (2 * tr + i) * HDIM + 2 * tc) = v;
                    }
                }
            }
        }
}

// ---------------------------------------------------------------------------
extern "C" void kernel_launch(void* const* d_in, const int* in_sizes, int n_in,
                              void* d_out, int out_size) {
    const float* x     = (const float*)d_in[0];
    const float* convs = (const float*)d_in[1];
    const float* w1    = (const float*)d_in[2];
    const float* b1    = (const float*)d_in[3];
    const float* w2    = (const float*)d_in[4];
    const float* b2    = (const float*)d_in[5];
    float* out = (float*)d_out;
    (void)in_sizes; (void)n_in; (void)out_size;

    cudaFuncSetAttribute(wgemm_kernel,
                         cudaFuncAttributeMaxDynamicSharedMemorySize, SMEM_DYN);
    cudaFuncSetAttribute(vtrans_kernel,
                         cudaFuncAttributeMaxDynamicSharedMemorySize, VT_SMEM);

    xborder_kernel<<<B_, 256>>>();
    xsplit_kernel<<<dim3(98, B_), 256>>>(x);
    router_kernel<<<B_, 32>>>(w1, b1, w2, b2);
    umix_kernel<<<dim3(COUT, 4), 128>>>(convs);
    vtrans_kernel<<<dim3(28, B_), 256, VT_SMEM>>>();
    wgemm_kernel<<<dim3(TTILES, 2, B_), 512, SMEM_DYN>>>(out);
}